// round 15
// baseline (speedup 1.0000x reference)
#include <cuda_runtime.h>
#include <cuda_bf16.h>
#include <cstdint>
#include <math.h>

// Problem constants
#define S_LEN 2048
#define D_DIM 2048
#define B_SZ  2
#define NH    16
#define HD    128
#define M_FF  8192
#define ROWS  (B_SZ * S_LEN)   // 4096

typedef __nv_bfloat16 bf16;

// -------------------- scratch (device globals; no allocation allowed) -----
__device__ __align__(16) int8_t g_h_q1  [ROWS * D_DIM];
__device__ __align__(16) int8_t g_h_q2  [ROWS * D_DIM];
__device__            float  g_h_s   [ROWS];
__device__ __align__(16) float g_attn  [ROWS * D_DIM];
__device__ __align__(16) int8_t g_at_q1 [ROWS * D_DIM];
__device__ __align__(16) int8_t g_at_q2 [ROWS * D_DIM];
__device__            float  g_at_s  [ROWS];
__device__            float  g_at_rm [ROWS];
__device__ __align__(16) float g_x2    [ROWS * D_DIM];
__device__ __align__(16) float g_ff    [ROWS * M_FF];
__device__ __align__(16) int8_t g_ff_q1 [ROWS * M_FF];
__device__ __align__(16) int8_t g_ff_q2 [ROWS * M_FF];
__device__            float  g_ff_s  [ROWS];
__device__            float  g_ff_rm [ROWS];
// attention operands (flat quirk layout; scales at [row*16+seg] == [bh*S+j])
__device__ __align__(16) int8_t g_q_q1  [ROWS * D_DIM];
__device__ __align__(16) int8_t g_q_q2  [ROWS * D_DIM];
__device__            float  g_q_sc  [ROWS * NH];
__device__ __align__(16) int8_t g_k_q1  [ROWS * D_DIM];
__device__ __align__(16) int8_t g_k_q2  [ROWS * D_DIM];
__device__            float  g_k_sc  [ROWS * NH];
__device__ __align__(16) bf16  g_vbf   [ROWS * D_DIM];
__device__ __align__(16) bf16  g_vt    [B_SZ * NH * HD * S_LEN];
// int8 2-limb weights ([N][K]); Wq+Wk stacked
__device__ __align__(16) int8_t g_wqk_q1 [2 * D_DIM * D_DIM];
__device__ __align__(16) int8_t g_wqk_q2 [2 * D_DIM * D_DIM];
__device__            float  g_wqk_s  [2 * D_DIM];
__device__ __align__(16) int8_t g_wv_q1 [D_DIM * D_DIM];
__device__ __align__(16) int8_t g_wv_q2 [D_DIM * D_DIM];
__device__            float  g_wv_s  [D_DIM];
__device__ __align__(16) int8_t g_wo_q1 [D_DIM * D_DIM];
__device__ __align__(16) int8_t g_wo_q2 [D_DIM * D_DIM];
__device__            float  g_wo_s  [D_DIM];
__device__ __align__(16) int8_t g_w1_q1 [M_FF * D_DIM];
__device__ __align__(16) int8_t g_w1_q2 [M_FF * D_DIM];
__device__            float  g_w1_s  [M_FF];
__device__ __align__(16) int8_t g_w2_q1 [D_DIM * M_FF];
__device__ __align__(16) int8_t g_w2_q2 [D_DIM * M_FF];
__device__            float  g_w2_s  [D_DIM];

// ===========================================================================
// helpers
// ===========================================================================
__device__ __forceinline__ uint32_t smem_u32(const void* p) {
    uint32_t a;
    asm("{ .reg .u64 t; cvta.to.shared.u64 t, %1; cvt.u32.u64 %0, t; }" : "=r"(a) : "l"(p));
    return a;
}
__device__ __forceinline__ void cpa16(uint32_t dst, const void* src) {
    asm volatile("cp.async.cg.shared.global [%0], [%1], 16;" :: "r"(dst), "l"(src));
}
#define CP_COMMIT() asm volatile("cp.async.commit_group;" ::: "memory")
#define CP_WAIT1()  asm volatile("cp.async.wait_group 1;" ::: "memory")
#define CP_WAIT0()  asm volatile("cp.async.wait_group 0;" ::: "memory")

__device__ __forceinline__ void ldmx4(uint32_t* r, uint32_t addr) {
    asm volatile("ldmatrix.sync.aligned.m8n8.x4.shared.b16 {%0,%1,%2,%3}, [%4];"
        : "=r"(r[0]), "=r"(r[1]), "=r"(r[2]), "=r"(r[3]) : "r"(addr));
}
__device__ __forceinline__ void mma_bf16(float* d, const uint32_t* a, uint32_t b0, uint32_t b1) {
    asm volatile(
        "mma.sync.aligned.m16n8k16.row.col.f32.bf16.bf16.f32 "
        "{%0,%1,%2,%3},{%4,%5,%6,%7},{%8,%9},{%0,%1,%2,%3};"
        : "+f"(d[0]), "+f"(d[1]), "+f"(d[2]), "+f"(d[3])
        : "r"(a[0]), "r"(a[1]), "r"(a[2]), "r"(a[3]), "r"(b0), "r"(b1));
}
__device__ __forceinline__ void mma_s8(int* d, const uint32_t* a, uint32_t b0, uint32_t b1) {
    asm volatile(
        "mma.sync.aligned.m16n8k32.row.col.s32.s8.s8.s32 "
        "{%0,%1,%2,%3},{%4,%5,%6,%7},{%8,%9},{%0,%1,%2,%3};"
        : "+r"(d[0]), "+r"(d[1]), "+r"(d[2]), "+r"(d[3])
        : "r"(a[0]), "r"(a[1]), "r"(a[2]), "r"(a[3]), "r"(b0), "r"(b1));
}
__device__ __forceinline__ void quant2(float v, float inv_s, int8_t& h, int8_t& l) {
    float q  = v * inv_s;
    float q1 = rintf(q);
    float q2 = rintf((q - q1) * 256.0f);
    q2 = fminf(fmaxf(q2, -127.0f), 127.0f);
    h = (int8_t)(int)q1;
    l = (int8_t)(int)q2;
}

// ===========================================================================
// fused column-absmax + transpose + int8 2-limb quant (weights, one pass set)
// block = 32-column strip; phase 1 colmax (DRAM), phase 2 quantize (mostly L2)
// ===========================================================================
__global__ __launch_bounds__(256)
void colquant_i8(const float* __restrict__ in, int R, int C,
                 int8_t* __restrict__ q1o, int8_t* __restrict__ q2o,
                 float* __restrict__ sOut)
{
    __shared__ float tile[32][33];
    __shared__ float red[8][33];
    __shared__ float cmax[32];
    const int tx = threadIdx.x & 31;
    const int ty = threadIdx.x >> 5;
    const int bx = blockIdx.x * 32;

    // phase 1: column absmax over all R rows
    float m = 0.f;
    for (int r = ty; r < R; r += 8)
        m = fmaxf(m, fabsf(in[(size_t)r * C + bx + tx]));
    red[ty][tx] = m;
    __syncthreads();
    if (ty == 0) {
        float mm = red[0][tx];
#pragma unroll
        for (int r = 1; r < 8; ++r) mm = fmaxf(mm, red[r][tx]);
        mm = fmaxf(mm, 1e-20f);
        cmax[tx] = mm;
        sOut[bx + tx] = mm * (1.0f / 127.0f);
    }
    __syncthreads();

    // phase 2: transpose + quantize (rows re-read, mostly L2-resident)
    for (int by = 0; by < R; by += 32) {
#pragma unroll
        for (int j = 0; j < 32; j += 8)
            tile[ty + j][tx] = in[(size_t)(by + ty + j) * C + bx + tx];
        __syncthreads();
#pragma unroll
        for (int j = 0; j < 32; j += 8) {
            const int orow = bx + ty + j;
            const float inv = 127.0f / cmax[ty + j];
            float v = tile[tx][ty + j];
            int8_t h, l; quant2(v, inv, h, l);
            size_t o = (size_t)orow * R + by + tx;
            q1o[o] = h; q2o[o] = l;
        }
        __syncthreads();
    }
}

// ===========================================================================
// quantize-only rowquant: uses precomputed row absmax
// ===========================================================================
__global__ __launch_bounds__(256)
void rowquant_pre(const float* __restrict__ in, int Kd, const float* __restrict__ rmax,
                  int8_t* __restrict__ q1, int8_t* __restrict__ q2, float* __restrict__ s)
{
    const int row = blockIdx.x;
    const int tid = threadIdx.x;
    const float mm = fmaxf(rmax[row], 1e-20f);
    if (tid == 0) s[row] = mm * (1.0f / 127.0f);
    const float inv = 127.0f / mm;
    const float* r = in + (size_t)row * Kd;
    for (int c = tid; c < Kd; c += 256) {
        int8_t h, l; quant2(r[c], inv, h, l);
        q1[(size_t)row * Kd + c] = h;
        q2[(size_t)row * Kd + c] = l;
    }
}

// ===========================================================================
// V^T split (bf16)
// ===========================================================================
__global__ __launch_bounds__(256)
void vt_split(const bf16* __restrict__ v, bf16* __restrict__ vt)
{
    __shared__ bf16 tile[32][34];
    const int tx = threadIdx.x & 31;
    const int ty = threadIdx.x >> 5;
    const int bh = blockIdx.z;
    const int j0 = blockIdx.x * 32, c0 = blockIdx.y * 32;
    const bf16* vb = v + (size_t)bh * S_LEN * HD;
#pragma unroll
    for (int jj = 0; jj < 32; jj += 8)
        tile[ty + jj][tx] = vb[(size_t)(j0 + ty + jj) * HD + c0 + tx];
    __syncthreads();
#pragma unroll
    for (int jj = 0; jj < 32; jj += 8)
        vt[((size_t)bh * HD + c0 + ty + jj) * S_LEN + j0 + tx] = tile[tx][ty + jj];
}

// ===========================================================================
// LayerNorm + int8 2-limb quant
// ===========================================================================
__global__ __launch_bounds__(256)
void ln_quant_i8(const float* __restrict__ x, const float* __restrict__ gam,
                 const float* __restrict__ bet, int8_t* __restrict__ q1,
                 int8_t* __restrict__ q2, float* __restrict__ sArr)
{
    __shared__ float red[9];
    const int row = blockIdx.x;
    const int tid = threadIdx.x;
    const float* xr = x + (size_t)row * D_DIM;

    float v[8];
    float sum = 0.f;
#pragma unroll
    for (int i = 0; i < 8; ++i) { v[i] = xr[tid + 256 * i]; sum += v[i]; }
#pragma unroll
    for (int d = 16; d > 0; d >>= 1) sum += __shfl_xor_sync(0xffffffffu, sum, d);
    if ((tid & 31) == 0) red[tid >> 5] = sum;
    __syncthreads();
    float tot = 0.f;
#pragma unroll
    for (int i = 0; i < 8; ++i) tot += red[i];
    const float mean = tot * (1.0f / (float)D_DIM);

    float s2 = 0.f;
#pragma unroll
    for (int i = 0; i < 8; ++i) { float d = v[i] - mean; s2 += d * d; }
    __syncthreads();
#pragma unroll
    for (int d = 16; d > 0; d >>= 1) s2 += __shfl_xor_sync(0xffffffffu, s2, d);
    if ((tid & 31) == 0) red[tid >> 5] = s2;
    __syncthreads();
    tot = 0.f;
#pragma unroll
    for (int i = 0; i < 8; ++i) tot += red[i];
    const float rstd = rsqrtf(tot * (1.0f / (float)D_DIM) + 1e-5f);

    float o[8];
    float am = 0.f;
#pragma unroll
    for (int i = 0; i < 8; ++i) {
        int c = tid + 256 * i;
        o[i] = (v[i] - mean) * rstd * gam[c] + bet[c];
        am = fmaxf(am, fabsf(o[i]));
    }
    __syncthreads();
#pragma unroll
    for (int d = 16; d > 0; d >>= 1) am = fmaxf(am, __shfl_xor_sync(0xffffffffu, am, d));
    if ((tid & 31) == 0) red[tid >> 5] = am;
    __syncthreads();
    if (tid == 0) {
        float mm = red[0];
#pragma unroll
        for (int i = 1; i < 8; ++i) mm = fmaxf(mm, red[i]);
        mm = fmaxf(mm, 1e-20f);
        red[8] = mm;
        sArr[row] = mm * (1.0f / 127.0f);
    }
    __syncthreads();
    const float inv = 127.0f / red[8];
#pragma unroll
    for (int i = 0; i < 8; ++i) {
        int c = tid + 256 * i;
        int8_t h, l; quant2(o[i], inv, h, l);
        q1[(size_t)row * D_DIM + c] = h;
        q2[(size_t)row * D_DIM + c] = l;
    }
}

// ===========================================================================
// int8 2-limb tensor-core GEMM — 512 threads / 16 warps, warp tile 32x32.
// BK=64, 3-stage cp.async (96KB). EPI: 0 fp32 (+bias/relu/res, opt ROWMAX),
// 1 QK quantizing epilogue, 2 bf16 out.
// ===========================================================================
#define ISTAGE 32768
#define ISM_A2 8192
#define ISM_B1 16384
#define ISM_B2 24576
#define I8_SMEM (3 * ISTAGE)

template<int EPI, bool RELU, bool HAS_BIAS, bool HAS_RES, bool ROWMAX>
__global__ __launch_bounds__(512, 1)
void gemm_i8(const int8_t* __restrict__ A1, const int8_t* __restrict__ A2,
             const int8_t* __restrict__ B1, const int8_t* __restrict__ B2,
             const float* __restrict__ sA, const float* __restrict__ sB,
             const float* __restrict__ bias, const float* __restrict__ res,
             float* __restrict__ Cf, bf16* __restrict__ Obf, float* __restrict__ rowmax,
             int8_t* __restrict__ oq1a, int8_t* __restrict__ oq2a, float* __restrict__ osca,
             int8_t* __restrict__ oq1b, int8_t* __restrict__ oq2b, float* __restrict__ oscb,
             int Nd, int Kd)
{
    extern __shared__ char smem[];
    const uint32_t sb = smem_u32(smem);
    const int tid  = threadIdx.x;
    const int warp = tid >> 5;
    const int lane = tid & 31;
    const int wm   = warp & 3;
    const int wn   = warp >> 2;
    const int bx = blockIdx.x, by = blockIdx.y;
    const int ktiles = Kd >> 6;

    const int r0 = tid >> 2;
    const int cc = tid & 3;
    const int pc = (cc + (r0 >> 1)) & 3;
    const size_t gA0 = (size_t)(by * 128 + r0) * Kd + cc * 16;
    const size_t gB0 = (size_t)(bx * 128 + r0) * Kd + cc * 16;
    const int8_t* pA1 = A1 + gA0;  const int8_t* pA2 = A2 + gA0;
    const int8_t* pB1 = B1 + gB0;  const int8_t* pB2 = B2 + gB0;
    const uint32_t dA0 = (uint32_t)(r0 * 64 + pc * 16);

#define ISSUE_I8(slot, u) do { \
    uint32_t s0_ = sb + (slot) * ISTAGE; int ko_ = (u) * 64; \
    cpa16(s0_ + dA0,          pA1 + ko_); \
    cpa16(s0_ + dA0 + ISM_A2, pA2 + ko_); \
    cpa16(s0_ + dA0 + ISM_B1, pB1 + ko_); \
    cpa16(s0_ + dA0 + ISM_B2, pB2 + ko_); \
} while (0)

    const int l15   = lane & 15;
    const int chalf = lane >> 4;
    const uint32_t pc0 = (uint32_t)((chalf + (l15 >> 1)) & 3);
    const uint32_t pc1 = (uint32_t)((2 + chalf + (l15 >> 1)) & 3);
    const uint32_t offA[2] = { (uint32_t)((wm * 32 + l15) * 64) + pc0 * 16,
                               (uint32_t)((wm * 32 + l15) * 64) + pc1 * 16 };
    const uint32_t offB0[2] = { (uint32_t)((wn * 32 + l15) * 64) + pc0 * 16,
                                (uint32_t)((wn * 32 + l15) * 64) + pc1 * 16 };
    const uint32_t offB1[2] = { (uint32_t)((wn * 32 + 16 + l15) * 64) + pc0 * 16,
                                (uint32_t)((wn * 32 + 16 + l15) * 64) + pc1 * 16 };

    int accH[2][4][4], accM[2][4][4];
#pragma unroll
    for (int mt = 0; mt < 2; ++mt)
#pragma unroll
        for (int nt = 0; nt < 4; ++nt)
#pragma unroll
            for (int e = 0; e < 4; ++e) { accH[mt][nt][e] = 0; accM[mt][nt][e] = 0; }

    ISSUE_I8(0, 0); CP_COMMIT();
    ISSUE_I8(1, 1); CP_COMMIT();

    for (int t = 0; t < ktiles; ++t) {
        CP_WAIT1();
        __syncthreads();
        {
            const int u = t + 2;
            if (u < ktiles) { ISSUE_I8(u % 3, u); }
            CP_COMMIT();
        }
        const uint32_t st = sb + (t % 3) * ISTAGE;
#pragma unroll
        for (int j = 0; j < 2; ++j) {
            uint32_t b1F[8], b2F[8];
            ldmx4(&b1F[0], st + ISM_B1 + offB0[j]);
            ldmx4(&b1F[4], st + ISM_B1 + offB1[j]);
            ldmx4(&b2F[0], st + ISM_B2 + offB0[j]);
            ldmx4(&b2F[4], st + ISM_B2 + offB1[j]);
#pragma unroll
            for (int mt = 0; mt < 2; ++mt) {
                uint32_t a1F[4], a2F[4];
                ldmx4(a1F, st + mt * 1024 + offA[j]);
                ldmx4(a2F, st + ISM_A2 + mt * 1024 + offA[j]);
#pragma unroll
                for (int nt = 0; nt < 4; ++nt) {
                    const int p = (nt >> 1) * 4 + (nt & 1);
                    const uint32_t b0h = b1F[p], b1h = b1F[p + 2];
                    const uint32_t b0l = b2F[p], b1l = b2F[p + 2];
                    mma_s8(accH[mt][nt], a1F, b0h, b1h);
                    mma_s8(accM[mt][nt], a2F, b0h, b1h);
                    mma_s8(accM[mt][nt], a1F, b0l, b1l);
                }
            }
        }
    }

    const int g  = lane >> 2;
    const int tg = lane & 3;
    const float i256 = 0.00390625f;

    if (EPI == 1) {
        CP_WAIT0();
        __syncthreads();
        float* rmaxf = (float*)smem;
        if (tid < 128) rmaxf[tid] = 0.f;
        __syncthreads();
#pragma unroll
        for (int mt = 0; mt < 2; ++mt) {
            const int lrow = wm * 32 + mt * 16 + g;
            const int grow = by * 128 + lrow;
            const float sa0 = sA[grow], sa8 = sA[grow + 8];
            float am0 = 0.f, am1 = 0.f;
#pragma unroll
            for (int nt = 0; nt < 4; ++nt) {
                const int colg = bx * 128 + wn * 32 + nt * 8 + 2 * tg;
                const float sb0 = sB[colg], sb1 = sB[colg + 1];
                float v0 = sa0 * sb0 * ((float)accH[mt][nt][0] + (float)accM[mt][nt][0] * i256);
                float v1 = sa0 * sb1 * ((float)accH[mt][nt][1] + (float)accM[mt][nt][1] * i256);
                float v2 = sa8 * sb0 * ((float)accH[mt][nt][2] + (float)accM[mt][nt][2] * i256);
                float v3 = sa8 * sb1 * ((float)accH[mt][nt][3] + (float)accM[mt][nt][3] * i256);
                am0 = fmaxf(am0, fmaxf(fabsf(v0), fabsf(v1)));
                am1 = fmaxf(am1, fmaxf(fabsf(v2), fabsf(v3)));
            }
            atomicMax((unsigned int*)&rmaxf[lrow],     __float_as_uint(am0));
            atomicMax((unsigned int*)&rmaxf[lrow + 8], __float_as_uint(am1));
        }
        __syncthreads();
        const int seg = (bx < 16) ? bx : (bx - 16);
        int8_t* o1 = (bx < 16) ? oq1a : oq1b;
        int8_t* o2 = (bx < 16) ? oq2a : oq2b;
        float*  osc = (bx < 16) ? osca : oscb;
#pragma unroll
        for (int mt = 0; mt < 2; ++mt) {
            const int lrow = wm * 32 + mt * 16 + g;
            const size_t grow = (size_t)(by * 128 + lrow);
            const float sa0 = sA[grow], sa8 = sA[grow + 8];
            const float am0 = fmaxf(rmaxf[lrow], 1e-20f);
            const float am1 = fmaxf(rmaxf[lrow + 8], 1e-20f);
            const float inv0 = 127.0f / am0, inv1 = 127.0f / am1;
            if (wn == 0 && tg == 0) {
                osc[grow * 16 + seg]       = am0 * (1.0f / 127.0f);
                osc[(grow + 8) * 16 + seg] = am1 * (1.0f / 127.0f);
            }
#pragma unroll
            for (int nt = 0; nt < 4; ++nt) {
                const int colg = bx * 128 + wn * 32 + nt * 8 + 2 * tg;
                const int colo = seg * 128 + wn * 32 + nt * 8 + 2 * tg;
                const float sb0 = sB[colg], sb1 = sB[colg + 1];
                float v0 = sa0 * sb0 * ((float)accH[mt][nt][0] + (float)accM[mt][nt][0] * i256);
                float v1 = sa0 * sb1 * ((float)accH[mt][nt][1] + (float)accM[mt][nt][1] * i256);
                float v2 = sa8 * sb0 * ((float)accH[mt][nt][2] + (float)accM[mt][nt][2] * i256);
                float v3 = sa8 * sb1 * ((float)accH[mt][nt][3] + (float)accM[mt][nt][3] * i256);
                int8_t h0, l0, h1, l1;
                quant2(v0, inv0, h0, l0); quant2(v1, inv0, h1, l1);
                *(char2*)(o1 + grow * D_DIM + colo) = make_char2(h0, h1);
                *(char2*)(o2 + grow * D_DIM + colo) = make_char2(l0, l1);
                quant2(v2, inv1, h0, l0); quant2(v3, inv1, h1, l1);
                *(char2*)(o1 + (grow + 8) * D_DIM + colo) = make_char2(h0, h1);
                *(char2*)(o2 + (grow + 8) * D_DIM + colo) = make_char2(l0, l1);
            }
        }
        return;
    }

#pragma unroll
    for (int mt = 0; mt < 2; ++mt) {
        const int row = by * 128 + wm * 32 + mt * 16 + g;
        const float sa0 = sA[row], sa8 = sA[row + 8];
        float rm0 = 0.f, rm1 = 0.f;
#pragma unroll
        for (int nt = 0; nt < 4; ++nt) {
            const int col = bx * 128 + wn * 32 + nt * 8 + 2 * tg;
            const float sb0 = sB[col], sb1 = sB[col + 1];
            float v0 = sa0 * sb0 * ((float)accH[mt][nt][0] + (float)accM[mt][nt][0] * i256);
            float v1 = sa0 * sb1 * ((float)accH[mt][nt][1] + (float)accM[mt][nt][1] * i256);
            float v2 = sa8 * sb0 * ((float)accH[mt][nt][2] + (float)accM[mt][nt][2] * i256);
            float v3 = sa8 * sb1 * ((float)accH[mt][nt][3] + (float)accM[mt][nt][3] * i256);
            if (EPI == 2) {
                *(__nv_bfloat162*)(Obf + (size_t)row * Nd + col) =
                    __nv_bfloat162(__float2bfloat16_rn(v0), __float2bfloat16_rn(v1));
                *(__nv_bfloat162*)(Obf + (size_t)(row + 8) * Nd + col) =
                    __nv_bfloat162(__float2bfloat16_rn(v2), __float2bfloat16_rn(v3));
            } else {
                if (HAS_BIAS) {
                    float2 b2v = *(const float2*)(bias + col);
                    v0 += b2v.x; v1 += b2v.y; v2 += b2v.x; v3 += b2v.y;
                }
                if (RELU) {
                    v0 = fmaxf(v0, 0.f); v1 = fmaxf(v1, 0.f);
                    v2 = fmaxf(v2, 0.f); v3 = fmaxf(v3, 0.f);
                }
                if (HAS_RES) {
                    float2 ra = *(const float2*)(res + (size_t)row * Nd + col);
                    float2 rb = *(const float2*)(res + (size_t)(row + 8) * Nd + col);
                    v0 += ra.x; v1 += ra.y; v2 += rb.x; v3 += rb.y;
                }
                if (ROWMAX) {
                    rm0 = fmaxf(rm0, fmaxf(fabsf(v0), fabsf(v1)));
                    rm1 = fmaxf(rm1, fmaxf(fabsf(v2), fabsf(v3)));
                }
                *(float2*)(Cf + (size_t)row * Nd + col)       = make_float2(v0, v1);
                *(float2*)(Cf + (size_t)(row + 8) * Nd + col) = make_float2(v2, v3);
            }
        }
        if (EPI == 0 && ROWMAX) {
            rm0 = fmaxf(rm0, __shfl_xor_sync(0xffffffffu, rm0, 1));
            rm0 = fmaxf(rm0, __shfl_xor_sync(0xffffffffu, rm0, 2));
            rm1 = fmaxf(rm1, __shfl_xor_sync(0xffffffffu, rm1, 1));
            rm1 = fmaxf(rm1, __shfl_xor_sync(0xffffffffu, rm1, 2));
            if (tg == 0) {
                atomicMax((unsigned int*)&rowmax[row],     __float_as_uint(rm0));
                atomicMax((unsigned int*)&rowmax[row + 8], __float_as_uint(rm1));
            }
        }
    }
#undef ISSUE_I8
}

// ===========================================================================
// Tensor-core flash attention (QUIRK layout); epilogue feeds row absmax.
// ===========================================================================
#define AQ_H  0
#define AQ_L  18432
#define AK_H(bf) (36864 + (bf) * 18432)
#define AK_L(bf) (AK_H(bf) + 9216)
#define AVT(bf)  (73728 + (bf) * 18432)
#define APS_H 110592
#define APS_L 129024
#define ASQ   147456
#define ASK(bf) (147968 + (bf) * 256)
#define ATT_SMEM 148480

__global__ __launch_bounds__(256)
void attn_i8(const int8_t* __restrict__ Qq1, const int8_t* __restrict__ Qq2,
             const float* __restrict__ Qs,
             const int8_t* __restrict__ Kq1, const int8_t* __restrict__ Kq2,
             const float* __restrict__ Ks,
             const bf16* __restrict__ VT, float* __restrict__ O,
             float* __restrict__ rowmax)
{
    extern __shared__ char smem[];
    const uint32_t sb = smem_u32(smem);
    float* sQf = (float*)(smem + ASQ);
    const int qt   = blockIdx.x;
    const int head = blockIdx.y;
    const int b    = blockIdx.z;
    const int tid  = threadIdx.x;
    const int warp = tid >> 5;
    const int lane = tid & 31;
    const int l15  = lane & 15;
    const int lhalf = lane >> 4;
    const int g  = lane >> 2;
    const int tg = lane & 3;
    const int mrow = warp * 16;
    const int ntiles = 2 * qt + 2;
    const int bh = b * NH + head;
    const size_t hbase = (size_t)bh * S_LEN * HD;
    const int i0 = qt * 128;
    const bf16* vth = VT + (size_t)bh * HD * S_LEN;

    if (tid < 128) sQf[tid] = Qs[(size_t)bh * S_LEN + i0 + tid];

#pragma unroll
    for (int i = 0; i < 4; ++i) {
        int id = tid + 256 * i;
        int r = id >> 3, c = (id & 7) * 16;
        cpa16(sb + AQ_H + r * 144 + c, Qq1 + hbase + (size_t)(i0 + r) * HD + c);
        cpa16(sb + AQ_L + r * 144 + c, Qq2 + hbase + (size_t)(i0 + r) * HD + c);
    }

#define ATT_ISSUE(bf_, jt_) do { \
    const size_t kj0_ = (size_t)(jt_) * 64; \
    for (int i_ = tid; i_ < 512; i_ += 256) { \
        int r_ = i_ >> 3, c_ = (i_ & 7) * 16; \
        cpa16(sb + AK_H(bf_) + r_ * 144 + c_, Kq1 + hbase + (kj0_ + r_) * HD + c_); \
        cpa16(sb + AK_L(bf_) + r_ * 144 + c_, Kq2 + hbase + (kj0_ + r_) * HD + c_); \
    } \
    for (int i_ = tid; i_ < 1024; i_ += 256) { \
        int r_ = i_ >> 3, c_ = (i_ & 7) * 16; \
        cpa16(sb + AVT(bf_) + r_ * 144 + c_, \
              (const char*)(vth + (size_t)r_ * S_LEN + kj0_) + c_); \
    } \
    if (tid < 64) ((float*)(smem + ASK(bf_)))[tid] = Ks[(size_t)bh * S_LEN + kj0_ + tid]; \
} while (0)

    ATT_ISSUE(0, 0); CP_COMMIT();
    ATT_ISSUE(1, 1); CP_COMMIT();

    float o_acc[16][4];
#pragma unroll
    for (int ot = 0; ot < 16; ++ot)
#pragma unroll
        for (int e = 0; e < 4; ++e) o_acc[ot][e] = 0.f;
    float m0 = -1e30f, m1 = -1e30f, l0 = 0.f, l1 = 0.f;
    const float inv_sqrt_d = 0.08838834764831845f;
    const float inv256 = 0.00390625f;
    const int i_g0 = i0 + mrow + g;
    const int i_g1 = i_g0 + 8;

    const uint32_t qbH = sb + AQ_H + (mrow + l15) * 144 + lhalf * 16;
    const uint32_t qbL = sb + AQ_L + (mrow + l15) * 144 + lhalf * 16;
    const uint32_t pbH = sb + APS_H + (mrow + l15) * 144 + lhalf * 16;
    const uint32_t pbL = sb + APS_L + (mrow + l15) * 144 + lhalf * 16;

    for (int jt = 0; jt < ntiles; ++jt) {
        const int buf = jt & 1;
        CP_WAIT1();
        __syncthreads();
        const float* sKf = (const float*)(smem + ASK(buf));

        int accH[8][4], accM[8][4];
#pragma unroll
        for (int nt = 0; nt < 8; ++nt)
#pragma unroll
            for (int e = 0; e < 4; ++e) { accH[nt][e] = 0; accM[nt][e] = 0; }

#pragma unroll
        for (int ks = 0; ks < 4; ++ks) {
            uint32_t aH[4], aL[4];
            ldmx4(aH, qbH + ks * 32);
            ldmx4(aL, qbL + ks * 32);
#pragma unroll
            for (int ng = 0; ng < 4; ++ng) {
                uint32_t bH4[4], bL4[4];
                const uint32_t kaddr = (uint32_t)((ng * 16 + l15) * 144) + lhalf * 16 + ks * 32;
                ldmx4(bH4, sb + AK_H(buf) + kaddr);
                ldmx4(bL4, sb + AK_L(buf) + kaddr);
                mma_s8(accH[2 * ng],     aH, bH4[0], bH4[2]);
                mma_s8(accM[2 * ng],     aL, bH4[0], bH4[2]);
                mma_s8(accM[2 * ng],     aH, bL4[0], bL4[2]);
                mma_s8(accH[2 * ng + 1], aH, bH4[1], bH4[3]);
                mma_s8(accM[2 * ng + 1], aL, bH4[1], bH4[3]);
                mma_s8(accM[2 * ng + 1], aH, bL4[1], bL4[3]);
            }
        }

        const float sq0 = sQf[mrow + g], sq1 = sQf[mrow + g + 8];
        const bool diag = (jt >= 2 * qt);
        float sv[8][4];
        float rm0 = -1e30f, rm1 = -1e30f;
#pragma unroll
        for (int nt = 0; nt < 8; ++nt) {
            const int col0 = nt * 8 + 2 * tg;
            const float sk0 = sKf[col0], sk1 = sKf[col0 + 1];
            float s00 = sq0 * sk0 * ((float)accH[nt][0] + (float)accM[nt][0] * inv256);
            float s01 = sq0 * sk1 * ((float)accH[nt][1] + (float)accM[nt][1] * inv256);
            float s10 = sq1 * sk0 * ((float)accH[nt][2] + (float)accM[nt][2] * inv256);
            float s11 = sq1 * sk1 * ((float)accH[nt][3] + (float)accM[nt][3] * inv256);
            if (diag) {
                const int j0g = jt * 64 + col0;
                if (j0g     > i_g0) s00 = -1e9f;
                if (j0g + 1 > i_g0) s01 = -1e9f;
                if (j0g     > i_g1) s10 = -1e9f;
                if (j0g + 1 > i_g1) s11 = -1e9f;
            }
            s00 *= inv_sqrt_d; s01 *= inv_sqrt_d; s10 *= inv_sqrt_d; s11 *= inv_sqrt_d;
            sv[nt][0] = s00; sv[nt][1] = s01; sv[nt][2] = s10; sv[nt][3] = s11;
            rm0 = fmaxf(rm0, fmaxf(s00, s01));
            rm1 = fmaxf(rm1, fmaxf(s10, s11));
        }
        rm0 = fmaxf(rm0, __shfl_xor_sync(0xffffffffu, rm0, 1));
        rm0 = fmaxf(rm0, __shfl_xor_sync(0xffffffffu, rm0, 2));
        rm1 = fmaxf(rm1, __shfl_xor_sync(0xffffffffu, rm1, 1));
        rm1 = fmaxf(rm1, __shfl_xor_sync(0xffffffffu, rm1, 2));
        const float mn0 = fmaxf(m0, rm0), mn1 = fmaxf(m1, rm1);
        const float cr0 = __expf(m0 - mn0), cr1 = __expf(m1 - mn1);
        m0 = mn0; m1 = mn1;
        float rs0 = 0.f, rs1 = 0.f;
#pragma unroll
        for (int nt = 0; nt < 8; ++nt) {
            float p00 = __expf(sv[nt][0] - mn0);
            float p01 = __expf(sv[nt][1] - mn0);
            float p10 = __expf(sv[nt][2] - mn1);
            float p11 = __expf(sv[nt][3] - mn1);
            rs0 += p00 + p01; rs1 += p10 + p11;
            bf16 h00 = __float2bfloat16_rn(p00), h01 = __float2bfloat16_rn(p01);
            bf16 h10 = __float2bfloat16_rn(p10), h11 = __float2bfloat16_rn(p11);
            bf16 l00b = __float2bfloat16_rn(p00 - __bfloat162float(h00));
            bf16 l01b = __float2bfloat16_rn(p01 - __bfloat162float(h01));
            bf16 l10b = __float2bfloat16_rn(p10 - __bfloat162float(h10));
            bf16 l11b = __float2bfloat16_rn(p11 - __bfloat162float(h11));
            const uint32_t cofs = (uint32_t)((nt * 8 + 2 * tg) * 2);
            *(__nv_bfloat162*)(smem + APS_H + (mrow + g) * 144 + cofs)     = __nv_bfloat162(h00, h01);
            *(__nv_bfloat162*)(smem + APS_H + (mrow + g + 8) * 144 + cofs) = __nv_bfloat162(h10, h11);
            *(__nv_bfloat162*)(smem + APS_L + (mrow + g) * 144 + cofs)     = __nv_bfloat162(l00b, l01b);
            *(__nv_bfloat162*)(smem + APS_L + (mrow + g + 8) * 144 + cofs) = __nv_bfloat162(l10b, l11b);
        }
        rs0 += __shfl_xor_sync(0xffffffffu, rs0, 1);
        rs0 += __shfl_xor_sync(0xffffffffu, rs0, 2);
        rs1 += __shfl_xor_sync(0xffffffffu, rs1, 1);
        rs1 += __shfl_xor_sync(0xffffffffu, rs1, 2);
        l0 = l0 * cr0 + rs0;
        l1 = l1 * cr1 + rs1;
#pragma unroll
        for (int ot = 0; ot < 16; ++ot) {
            o_acc[ot][0] *= cr0; o_acc[ot][1] *= cr0;
            o_acc[ot][2] *= cr1; o_acc[ot][3] *= cr1;
        }
        __syncwarp();

#pragma unroll
        for (int ks = 0; ks < 4; ++ks) {
            uint32_t aH[4], aL[4];
            ldmx4(aH, pbH + ks * 32);
            ldmx4(aL, pbL + ks * 32);
#pragma unroll
            for (int vg = 0; vg < 8; ++vg) {
                uint32_t vb[4];
                ldmx4(vb, sb + AVT(buf) + (uint32_t)((vg * 16 + l15) * 144) + lhalf * 16 + ks * 32);
                mma_bf16(o_acc[2 * vg],     aH, vb[0], vb[2]);
                mma_bf16(o_acc[2 * vg],     aL, vb[0], vb[2]);
                mma_bf16(o_acc[2 * vg + 1], aH, vb[1], vb[3]);
                mma_bf16(o_acc[2 * vg + 1], aL, vb[1], vb[3]);
            }
        }
        __syncthreads();
        if (jt + 2 < ntiles) { ATT_ISSUE(buf, jt + 2); }
        CP_COMMIT();
    }

    const float li0 = 1.0f / l0, li1 = 1.0f / l1;
    const size_t grow0 = (size_t)b * S_LEN + i0 + mrow + g;
    float* orow0 = O + grow0       * D_DIM + head * HD;
    float* orow1 = O + (grow0 + 8) * D_DIM + head * HD;
    float am0 = 0.f, am1 = 0.f;
#pragma unroll
    for (int ot = 0; ot < 16; ++ot) {
        const int col = ot * 8 + 2 * tg;
        float a0 = o_acc[ot][0] * li0, a1 = o_acc[ot][1] * li0;
        float a2 = o_acc[ot][2] * li1, a3 = o_acc[ot][3] * li1;
        am0 = fmaxf(am0, fmaxf(fabsf(a0), fabsf(a1)));
        am1 = fmaxf(am1, fmaxf(fabsf(a2), fabsf(a3)));
        *(float2*)(orow0 + col) = make_float2(a0, a1);
        *(float2*)(orow1 + col) = make_float2(a2, a3);
    }
    am0 = fmaxf(am0, __shfl_xor_sync(0xffffffffu, am0, 1));
    am0 = fmaxf(am0, __shfl_xor_sync(0xffffffffu, am0, 2));
    am1 = fmaxf(am1, __shfl_xor_sync(0xffffffffu, am1, 1));
    am1 = fmaxf(am1, __shfl_xor_sync(0xffffffffu, am1, 2));
    if (tg == 0) {
        atomicMax((unsigned int*)&rowmax[grow0],     __float_as_uint(am0));
        atomicMax((unsigned int*)&rowmax[grow0 + 8], __float_as_uint(am1));
    }
#undef ATT_ISSUE
}

// ===========================================================================
// Launch
// ===========================================================================
extern "C" void kernel_launch(void* const* d_in, const int* in_sizes, int n_in,
                              void* d_out, int out_size)
{
    (void)in_sizes; (void)n_in; (void)out_size;
    const float* x    = (const float*)d_in[0];
    const float* Wq   = (const float*)d_in[2];
    const float* Wk   = (const float*)d_in[3];
    const float* Wv   = (const float*)d_in[4];
    const float* Wo   = (const float*)d_in[5];
    const float* ln1g = (const float*)d_in[6];
    const float* ln1b = (const float*)d_in[7];
    const float* W1   = (const float*)d_in[8];
    const float* b1   = (const float*)d_in[9];
    const float* W2   = (const float*)d_in[10];
    const float* b2   = (const float*)d_in[11];
    const float* ln2g = (const float*)d_in[12];
    const float* ln2b = (const float*)d_in[13];
    float* out = (float*)d_out;

    int8_t *hq1, *hq2, *atq1, *atq2, *ffq1, *ffq2;
    float *hs, *ats, *ffs, *atrm, *ffrm;
    float *attn, *x2, *ff;
    int8_t *qq1, *qq2, *kq1, *kq2;
    float *qsc, *ksc;
    bf16 *vbf, *vt;
    int8_t *wqkq1, *wqkq2, *wvq1, *wvq2, *woq1, *woq2, *w1q1, *w1q2, *w2q1, *w2q2;
    float *wqks, *wvs, *wos, *w1s, *w2s;
    cudaGetSymbolAddress((void**)&hq1,  g_h_q1);
    cudaGetSymbolAddress((void**)&hq2,  g_h_q2);
    cudaGetSymbolAddress((void**)&hs,   g_h_s);
    cudaGetSymbolAddress((void**)&attn, g_attn);
    cudaGetSymbolAddress((void**)&atq1, g_at_q1);
    cudaGetSymbolAddress((void**)&atq2, g_at_q2);
    cudaGetSymbolAddress((void**)&ats,  g_at_s);
    cudaGetSymbolAddress((void**)&atrm, g_at_rm);
    cudaGetSymbolAddress((void**)&x2,   g_x2);
    cudaGetSymbolAddress((void**)&ff,   g_ff);
    cudaGetSymbolAddress((void**)&ffq1, g_ff_q1);
    cudaGetSymbolAddress((void**)&ffq2, g_ff_q2);
    cudaGetSymbolAddress((void**)&ffs,  g_ff_s);
    cudaGetSymbolAddress((void**)&ffrm, g_ff_rm);
    cudaGetSymbolAddress((void**)&qq1,  g_q_q1);
    cudaGetSymbolAddress((void**)&qq2,  g_q_q2);
    cudaGetSymbolAddress((void**)&qsc,  g_q_sc);
    cudaGetSymbolAddress((void**)&kq1,  g_k_q1);
    cudaGetSymbolAddress((void**)&kq2,  g_k_q2);
    cudaGetSymbolAddress((void**)&ksc,  g_k_sc);
    cudaGetSymbolAddress((void**)&vbf,  g_vbf);
    cudaGetSymbolAddress((void**)&vt,   g_vt);
    cudaGetSymbolAddress((void**)&wqkq1, g_wqk_q1);
    cudaGetSymbolAddress((void**)&wqkq2, g_wqk_q2);
    cudaGetSymbolAddress((void**)&wqks,  g_wqk_s);
    cudaGetSymbolAddress((void**)&wvq1, g_wv_q1);
    cudaGetSymbolAddress((void**)&wvq2, g_wv_q2);
    cudaGetSymbolAddress((void**)&wvs,  g_wv_s);
    cudaGetSymbolAddress((void**)&woq1, g_wo_q1);
    cudaGetSymbolAddress((void**)&woq2, g_wo_q2);
    cudaGetSymbolAddress((void**)&wos,  g_wo_s);
    cudaGetSymbolAddress((void**)&w1q1, g_w1_q1);
    cudaGetSymbolAddress((void**)&w1q2, g_w1_q2);
    cudaGetSymbolAddress((void**)&w1s,  g_w1_s);
    cudaGetSymbolAddress((void**)&w2q1, g_w2_q1);
    cudaGetSymbolAddress((void**)&w2q2, g_w2_q2);
    cudaGetSymbolAddress((void**)&w2s,  g_w2_s);

    cudaFuncSetAttribute(attn_i8,
                         cudaFuncAttributeMaxDynamicSharedMemorySize, ATT_SMEM);
    cudaFuncSetAttribute(gemm_i8<0, false, false, true, false>,
                         cudaFuncAttributeMaxDynamicSharedMemorySize, I8_SMEM);
    cudaFuncSetAttribute(gemm_i8<0, true, true, false, true>,
                         cudaFuncAttributeMaxDynamicSharedMemorySize, I8_SMEM);
    cudaFuncSetAttribute(gemm_i8<0, false, true, true, false>,
                         cudaFuncAttributeMaxDynamicSharedMemorySize, I8_SMEM);
    cudaFuncSetAttribute(gemm_i8<1, false, false, false, false>,
                         cudaFuncAttributeMaxDynamicSharedMemorySize, I8_SMEM);
    cudaFuncSetAttribute(gemm_i8<2, false, false, false, false>,
                         cudaFuncAttributeMaxDynamicSharedMemorySize, I8_SMEM);

    const dim3 blk(256);
    const dim3 blkG(512);
    const dim3 gQK(32, 32);
    const dim3 gDD(D_DIM / 128, ROWS / 128);
    const dim3 gDM(M_FF / 128,  ROWS / 128);

    // ---- phase 1: LN1 + attention-side weight prep (fused 1-kernel each) ----
    ln_quant_i8<<<ROWS, blk>>>(x, ln1g, ln1b, hq1, hq2, hs);               // k1
    colquant_i8<<<64, blk>>>(Wq, D_DIM, D_DIM, wqkq1, wqkq2, wqks);        // k2
    colquant_i8<<<64, blk>>>(Wk, D_DIM, D_DIM,
        wqkq1 + (size_t)D_DIM * D_DIM, wqkq2 + (size_t)D_DIM * D_DIM,
        wqks + D_DIM);                                                      // k3
    colquant_i8<<<64, blk>>>(Wv, D_DIM, D_DIM, wvq1, wvq2, wvs);           // k4
    colquant_i8<<<64, blk>>>(Wo, D_DIM, D_DIM, woq1, woq2, wos);           // k5
    // QK combined GEMM with fused quantizing epilogue                      // k6 (ncu target)
    gemm_i8<1, false, false, false, false><<<gQK, blkG, I8_SMEM>>>(
        hq1, hq2, wqkq1, wqkq2, hs, wqks, nullptr, nullptr, nullptr, nullptr, nullptr,
        qq1, qq2, qsc, kq1, kq2, ksc, 2 * D_DIM, D_DIM);
    cudaMemsetAsync(atrm, 0, ROWS * sizeof(float));
    cudaMemsetAsync(ffrm, 0, ROWS * sizeof(float));
    gemm_i8<2, false, false, false, false><<<gDD, blkG, I8_SMEM>>>(
        hq1, hq2, wvq1, wvq2, hs, wvs, nullptr, nullptr, nullptr, vbf, nullptr,
        nullptr, nullptr, nullptr, nullptr, nullptr, nullptr, D_DIM, D_DIM);
    vt_split<<<dim3(S_LEN / 32, HD / 32, B_SZ * NH), blk>>>(vbf, vt);
    attn_i8<<<dim3(S_LEN / 128, NH, B_SZ), blk, ATT_SMEM>>>(
        qq1, qq2, qsc, kq1, kq2, ksc, vt, attn, atrm);
    rowquant_pre<<<ROWS, blk>>>(attn, D_DIM, atrm, atq1, atq2, ats);
    gemm_i8<0, false, false, true, false><<<gDD, blkG, I8_SMEM>>>(
        atq1, atq2, woq1, woq2, ats, wos, nullptr, x, x2, nullptr, nullptr,
        nullptr, nullptr, nullptr, nullptr, nullptr, nullptr, D_DIM, D_DIM);
    // ---- phase 2: FFN ----
    ln_quant_i8<<<ROWS, blk>>>(x2, ln2g, ln2b, hq1, hq2, hs);
    colquant_i8<<<256, blk>>>(W1, D_DIM, M_FF, w1q1, w1q2, w1s);
    colquant_i8<<<64,  blk>>>(W2, M_FF, D_DIM, w2q1, w2q2, w2s);
    gemm_i8<0, true, true, false, true><<<gDM, blkG, I8_SMEM>>>(
        hq1, hq2, w1q1, w1q2, hs, w1s, b1, nullptr, ff, nullptr, ffrm,
        nullptr, nullptr, nullptr, nullptr, nullptr, nullptr, M_FF, D_DIM);
    rowquant_pre<<<ROWS, blk>>>(ff, M_FF, ffrm, ffq1, ffq2, ffs);
    gemm_i8<0, false, true, true, false><<<gDD, blkG, I8_SMEM>>>(
        ffq1, ffq2, w2q1, w2q2, ffs, w2s, b2, x2, out, nullptr, nullptr,
        nullptr, nullptr, nullptr, nullptr, nullptr, nullptr, D_DIM, M_FF);
}

// round 16
// speedup vs baseline: 1.1376x; 1.1376x over previous
#include <cuda_runtime.h>
#include <cuda_bf16.h>
#include <cstdint>
#include <math.h>

// Problem constants
#define S_LEN 2048
#define D_DIM 2048
#define B_SZ  2
#define NH    16
#define HD    128
#define M_FF  8192
#define ROWS  (B_SZ * S_LEN)   // 4096

typedef __nv_bfloat16 bf16;

// -------------------- scratch (device globals; no allocation allowed) -----
__device__ __align__(16) int8_t g_h_q1  [ROWS * D_DIM];
__device__ __align__(16) int8_t g_h_q2  [ROWS * D_DIM];
__device__            float  g_h_s   [ROWS];
__device__ __align__(16) float g_attn  [ROWS * D_DIM];
__device__ __align__(16) int8_t g_at_q1 [ROWS * D_DIM];
__device__ __align__(16) int8_t g_at_q2 [ROWS * D_DIM];
__device__            float  g_at_s  [ROWS];
__device__            float  g_at_rm [ROWS];
__device__ __align__(16) float g_x2    [ROWS * D_DIM];
__device__ __align__(16) float g_ff    [ROWS * M_FF];
__device__ __align__(16) int8_t g_ff_q1 [ROWS * M_FF];
__device__ __align__(16) int8_t g_ff_q2 [ROWS * M_FF];
__device__            float  g_ff_s  [ROWS];
__device__            float  g_ff_rm [ROWS];
// attention operands (flat quirk layout; scales at [row*16+seg] == [bh*S+j])
__device__ __align__(16) int8_t g_q_q1  [ROWS * D_DIM];
__device__ __align__(16) int8_t g_q_q2  [ROWS * D_DIM];
__device__            float  g_q_sc  [ROWS * NH];
__device__ __align__(16) int8_t g_k_q1  [ROWS * D_DIM];
__device__ __align__(16) int8_t g_k_q2  [ROWS * D_DIM];
__device__            float  g_k_sc  [ROWS * NH];
__device__ __align__(16) bf16  g_vbf   [ROWS * D_DIM];
__device__ __align__(16) bf16  g_vt    [B_SZ * NH * HD * S_LEN];
// int8 2-limb weights ([N][K]); Wq+Wk stacked
__device__ __align__(16) int8_t g_wqk_q1 [2 * D_DIM * D_DIM];
__device__ __align__(16) int8_t g_wqk_q2 [2 * D_DIM * D_DIM];
__device__            float  g_wqk_s  [2 * D_DIM];
__device__            float  g_wq_am [D_DIM];
__device__            float  g_wk_am [D_DIM];
__device__ __align__(16) int8_t g_wv_q1 [D_DIM * D_DIM];
__device__ __align__(16) int8_t g_wv_q2 [D_DIM * D_DIM];
__device__            float  g_wv_am [D_DIM];
__device__            float  g_wv_s  [D_DIM];
__device__ __align__(16) int8_t g_wo_q1 [D_DIM * D_DIM];
__device__ __align__(16) int8_t g_wo_q2 [D_DIM * D_DIM];
__device__            float  g_wo_am [D_DIM];
__device__            float  g_wo_s  [D_DIM];
__device__ __align__(16) int8_t g_w1_q1 [M_FF * D_DIM];
__device__ __align__(16) int8_t g_w1_q2 [M_FF * D_DIM];
__device__            float  g_w1_am [M_FF];
__device__            float  g_w1_s  [M_FF];
__device__ __align__(16) int8_t g_w2_q1 [D_DIM * M_FF];
__device__ __align__(16) int8_t g_w2_q2 [D_DIM * M_FF];
__device__            float  g_w2_am [D_DIM];
__device__            float  g_w2_s  [D_DIM];

// ===========================================================================
// helpers
// ===========================================================================
__device__ __forceinline__ uint32_t smem_u32(const void* p) {
    uint32_t a;
    asm("{ .reg .u64 t; cvta.to.shared.u64 t, %1; cvt.u32.u64 %0, t; }" : "=r"(a) : "l"(p));
    return a;
}
__device__ __forceinline__ void cpa16(uint32_t dst, const void* src) {
    asm volatile("cp.async.cg.shared.global [%0], [%1], 16;" :: "r"(dst), "l"(src));
}
#define CP_COMMIT() asm volatile("cp.async.commit_group;" ::: "memory")
#define CP_WAIT1()  asm volatile("cp.async.wait_group 1;" ::: "memory")
#define CP_WAIT0()  asm volatile("cp.async.wait_group 0;" ::: "memory")

__device__ __forceinline__ void ldmx4(uint32_t* r, uint32_t addr) {
    asm volatile("ldmatrix.sync.aligned.m8n8.x4.shared.b16 {%0,%1,%2,%3}, [%4];"
        : "=r"(r[0]), "=r"(r[1]), "=r"(r[2]), "=r"(r[3]) : "r"(addr));
}
__device__ __forceinline__ void mma_bf16(float* d, const uint32_t* a, uint32_t b0, uint32_t b1) {
    asm volatile(
        "mma.sync.aligned.m16n8k16.row.col.f32.bf16.bf16.f32 "
        "{%0,%1,%2,%3},{%4,%5,%6,%7},{%8,%9},{%0,%1,%2,%3};"
        : "+f"(d[0]), "+f"(d[1]), "+f"(d[2]), "+f"(d[3])
        : "r"(a[0]), "r"(a[1]), "r"(a[2]), "r"(a[3]), "r"(b0), "r"(b1));
}
__device__ __forceinline__ void mma_s8(int* d, const uint32_t* a, uint32_t b0, uint32_t b1) {
    asm volatile(
        "mma.sync.aligned.m16n8k32.row.col.s32.s8.s8.s32 "
        "{%0,%1,%2,%3},{%4,%5,%6,%7},{%8,%9},{%0,%1,%2,%3};"
        : "+r"(d[0]), "+r"(d[1]), "+r"(d[2]), "+r"(d[3])
        : "r"(a[0]), "r"(a[1]), "r"(a[2]), "r"(a[3]), "r"(b0), "r"(b1));
}
__device__ __forceinline__ void quant2(float v, float inv_s, int8_t& h, int8_t& l) {
    float q  = v * inv_s;
    float q1 = rintf(q);
    float q2 = rintf((q - q1) * 256.0f);
    q2 = fminf(fmaxf(q2, -127.0f), 127.0f);
    h = (int8_t)(int)q1;
    l = (int8_t)(int)q2;
}

// ===========================================================================
// per-column absmax
// ===========================================================================
__global__ __launch_bounds__(256)
void colamax_kernel(const float* __restrict__ in, int R, int C, float* __restrict__ amax)
{
    __shared__ float sm_[8][33];
    const int tx = threadIdx.x & 31;
    const int ty = threadIdx.x >> 5;
    const int bx = blockIdx.x * 32, by = blockIdx.y * 32;
    float m = 0.f;
#pragma unroll
    for (int j = 0; j < 4; ++j)
        m = fmaxf(m, fabsf(in[(size_t)(by + ty + 8 * j) * C + bx + tx]));
    sm_[ty][tx] = m;
    __syncthreads();
    if (ty == 0) {
        float mm = sm_[0][tx];
#pragma unroll
        for (int r = 1; r < 8; ++r) mm = fmaxf(mm, sm_[r][tx]);
        atomicMax((unsigned int*)&amax[bx + tx], __float_as_uint(mm));
    }
}

// ===========================================================================
// transpose + int8 2-limb quant (weights)
// ===========================================================================
__global__ __launch_bounds__(256)
void transpose_quant_i8(const float* __restrict__ in, const float* __restrict__ amax,
                        int8_t* __restrict__ q1o, int8_t* __restrict__ q2o,
                        float* __restrict__ sOut, int R, int C)
{
    __shared__ float tile[32][33];
    const int tx = threadIdx.x & 31;
    const int ty = threadIdx.x >> 5;
    const int bx = blockIdx.x * 32, by = blockIdx.y * 32;
#pragma unroll
    for (int j = 0; j < 32; j += 8)
        tile[ty + j][tx] = in[(size_t)(by + ty + j) * C + bx + tx];
    __syncthreads();
#pragma unroll
    for (int j = 0; j < 32; j += 8) {
        const int orow = bx + ty + j;
        float am = fmaxf(amax[orow], 1e-20f);
        float s  = am * (1.0f / 127.0f);
        float inv = 127.0f / am;
        if (tx == 0) sOut[orow] = s;
        float v = tile[tx][ty + j];
        int8_t h, l; quant2(v, inv, h, l);
        size_t o = (size_t)orow * R + by + tx;
        q1o[o] = h; q2o[o] = l;
    }
}

// ===========================================================================
// quantize-only rowquant: uses precomputed row absmax
// ===========================================================================
__global__ __launch_bounds__(256)
void rowquant_pre(const float* __restrict__ in, int Kd, const float* __restrict__ rmax,
                  int8_t* __restrict__ q1, int8_t* __restrict__ q2, float* __restrict__ s)
{
    const int row = blockIdx.x;
    const int tid = threadIdx.x;
    const float mm = fmaxf(rmax[row], 1e-20f);
    if (tid == 0) s[row] = mm * (1.0f / 127.0f);
    const float inv = 127.0f / mm;
    const float* r = in + (size_t)row * Kd;
    for (int c = tid; c < Kd; c += 256) {
        int8_t h, l; quant2(r[c], inv, h, l);
        q1[(size_t)row * Kd + c] = h;
        q2[(size_t)row * Kd + c] = l;
    }
}

// ===========================================================================
// V^T split (bf16)
// ===========================================================================
__global__ __launch_bounds__(256)
void vt_split(const bf16* __restrict__ v, bf16* __restrict__ vt)
{
    __shared__ bf16 tile[32][34];
    const int tx = threadIdx.x & 31;
    const int ty = threadIdx.x >> 5;
    const int bh = blockIdx.z;
    const int j0 = blockIdx.x * 32, c0 = blockIdx.y * 32;
    const bf16* vb = v + (size_t)bh * S_LEN * HD;
#pragma unroll
    for (int jj = 0; jj < 32; jj += 8)
        tile[ty + jj][tx] = vb[(size_t)(j0 + ty + jj) * HD + c0 + tx];
    __syncthreads();
#pragma unroll
    for (int jj = 0; jj < 32; jj += 8)
        vt[((size_t)bh * HD + c0 + ty + jj) * S_LEN + j0 + tx] = tile[tx][ty + jj];
}

// ===========================================================================
// LayerNorm + int8 2-limb quant
// ===========================================================================
__global__ __launch_bounds__(256)
void ln_quant_i8(const float* __restrict__ x, const float* __restrict__ gam,
                 const float* __restrict__ bet, int8_t* __restrict__ q1,
                 int8_t* __restrict__ q2, float* __restrict__ sArr)
{
    __shared__ float red[9];
    const int row = blockIdx.x;
    const int tid = threadIdx.x;
    const float* xr = x + (size_t)row * D_DIM;

    float v[8];
    float sum = 0.f;
#pragma unroll
    for (int i = 0; i < 8; ++i) { v[i] = xr[tid + 256 * i]; sum += v[i]; }
#pragma unroll
    for (int d = 16; d > 0; d >>= 1) sum += __shfl_xor_sync(0xffffffffu, sum, d);
    if ((tid & 31) == 0) red[tid >> 5] = sum;
    __syncthreads();
    float tot = 0.f;
#pragma unroll
    for (int i = 0; i < 8; ++i) tot += red[i];
    const float mean = tot * (1.0f / (float)D_DIM);

    float s2 = 0.f;
#pragma unroll
    for (int i = 0; i < 8; ++i) { float d = v[i] - mean; s2 += d * d; }
    __syncthreads();
#pragma unroll
    for (int d = 16; d > 0; d >>= 1) s2 += __shfl_xor_sync(0xffffffffu, s2, d);
    if ((tid & 31) == 0) red[tid >> 5] = s2;
    __syncthreads();
    tot = 0.f;
#pragma unroll
    for (int i = 0; i < 8; ++i) tot += red[i];
    const float rstd = rsqrtf(tot * (1.0f / (float)D_DIM) + 1e-5f);

    float o[8];
    float am = 0.f;
#pragma unroll
    for (int i = 0; i < 8; ++i) {
        int c = tid + 256 * i;
        o[i] = (v[i] - mean) * rstd * gam[c] + bet[c];
        am = fmaxf(am, fabsf(o[i]));
    }
    __syncthreads();
#pragma unroll
    for (int d = 16; d > 0; d >>= 1) am = fmaxf(am, __shfl_xor_sync(0xffffffffu, am, d));
    if ((tid & 31) == 0) red[tid >> 5] = am;
    __syncthreads();
    if (tid == 0) {
        float mm = red[0];
#pragma unroll
        for (int i = 1; i < 8; ++i) mm = fmaxf(mm, red[i]);
        mm = fmaxf(mm, 1e-20f);
        red[8] = mm;
        sArr[row] = mm * (1.0f / 127.0f);
    }
    __syncthreads();
    const float inv = 127.0f / red[8];
#pragma unroll
    for (int i = 0; i < 8; ++i) {
        int c = tid + 256 * i;
        int8_t h, l; quant2(o[i], inv, h, l);
        q1[(size_t)row * D_DIM + c] = h;
        q2[(size_t)row * D_DIM + c] = l;
    }
}

// ===========================================================================
// int8 2-limb tensor-core GEMM — 512 threads / 16 warps, warp tile 32x32.
// BK=64, 3-stage cp.async (96KB). EPI: 0 fp32 (+bias/relu/res, opt ROWMAX),
// 1 QK quantizing epilogue, 2 bf16 out.
// ===========================================================================
#define ISTAGE 32768
#define ISM_A2 8192
#define ISM_B1 16384
#define ISM_B2 24576
#define I8_SMEM (3 * ISTAGE)

template<int EPI, bool RELU, bool HAS_BIAS, bool HAS_RES, bool ROWMAX>
__global__ __launch_bounds__(512, 1)
void gemm_i8(const int8_t* __restrict__ A1, const int8_t* __restrict__ A2,
             const int8_t* __restrict__ B1, const int8_t* __restrict__ B2,
             const float* __restrict__ sA, const float* __restrict__ sB,
             const float* __restrict__ bias, const float* __restrict__ res,
             float* __restrict__ Cf, bf16* __restrict__ Obf, float* __restrict__ rowmax,
             int8_t* __restrict__ oq1a, int8_t* __restrict__ oq2a, float* __restrict__ osca,
             int8_t* __restrict__ oq1b, int8_t* __restrict__ oq2b, float* __restrict__ oscb,
             int Nd, int Kd)
{
    extern __shared__ char smem[];
    const uint32_t sb = smem_u32(smem);
    const int tid  = threadIdx.x;
    const int warp = tid >> 5;
    const int lane = tid & 31;
    const int wm   = warp & 3;
    const int wn   = warp >> 2;
    const int bx = blockIdx.x, by = blockIdx.y;
    const int ktiles = Kd >> 6;

    const int r0 = tid >> 2;
    const int cc = tid & 3;
    const int pc = (cc + (r0 >> 1)) & 3;
    const size_t gA0 = (size_t)(by * 128 + r0) * Kd + cc * 16;
    const size_t gB0 = (size_t)(bx * 128 + r0) * Kd + cc * 16;
    const int8_t* pA1 = A1 + gA0;  const int8_t* pA2 = A2 + gA0;
    const int8_t* pB1 = B1 + gB0;  const int8_t* pB2 = B2 + gB0;
    const uint32_t dA0 = (uint32_t)(r0 * 64 + pc * 16);

#define ISSUE_I8(slot, u) do { \
    uint32_t s0_ = sb + (slot) * ISTAGE; int ko_ = (u) * 64; \
    cpa16(s0_ + dA0,          pA1 + ko_); \
    cpa16(s0_ + dA0 + ISM_A2, pA2 + ko_); \
    cpa16(s0_ + dA0 + ISM_B1, pB1 + ko_); \
    cpa16(s0_ + dA0 + ISM_B2, pB2 + ko_); \
} while (0)

    const int l15   = lane & 15;
    const int chalf = lane >> 4;
    const uint32_t pc0 = (uint32_t)((chalf + (l15 >> 1)) & 3);
    const uint32_t pc1 = (uint32_t)((2 + chalf + (l15 >> 1)) & 3);
    const uint32_t offA[2] = { (uint32_t)((wm * 32 + l15) * 64) + pc0 * 16,
                               (uint32_t)((wm * 32 + l15) * 64) + pc1 * 16 };
    const uint32_t offB0[2] = { (uint32_t)((wn * 32 + l15) * 64) + pc0 * 16,
                                (uint32_t)((wn * 32 + l15) * 64) + pc1 * 16 };
    const uint32_t offB1[2] = { (uint32_t)((wn * 32 + 16 + l15) * 64) + pc0 * 16,
                                (uint32_t)((wn * 32 + 16 + l15) * 64) + pc1 * 16 };

    int accH[2][4][4], accM[2][4][4];
#pragma unroll
    for (int mt = 0; mt < 2; ++mt)
#pragma unroll
        for (int nt = 0; nt < 4; ++nt)
#pragma unroll
            for (int e = 0; e < 4; ++e) { accH[mt][nt][e] = 0; accM[mt][nt][e] = 0; }

    ISSUE_I8(0, 0); CP_COMMIT();
    ISSUE_I8(1, 1); CP_COMMIT();

    for (int t = 0; t < ktiles; ++t) {
        CP_WAIT1();
        __syncthreads();
        {
            const int u = t + 2;
            if (u < ktiles) { ISSUE_I8(u % 3, u); }
            CP_COMMIT();
        }
        const uint32_t st = sb + (t % 3) * ISTAGE;
#pragma unroll
        for (int j = 0; j < 2; ++j) {
            uint32_t b1F[8], b2F[8];
            ldmx4(&b1F[0], st + ISM_B1 + offB0[j]);
            ldmx4(&b1F[4], st + ISM_B1 + offB1[j]);
            ldmx4(&b2F[0], st + ISM_B2 + offB0[j]);
            ldmx4(&b2F[4], st + ISM_B2 + offB1[j]);
#pragma unroll
            for (int mt = 0; mt < 2; ++mt) {
                uint32_t a1F[4], a2F[4];
                ldmx4(a1F, st + mt * 1024 + offA[j]);
                ldmx4(a2F, st + ISM_A2 + mt * 1024 + offA[j]);
#pragma unroll
                for (int nt = 0; nt < 4; ++nt) {
                    const int p = (nt >> 1) * 4 + (nt & 1);
                    const uint32_t b0h = b1F[p], b1h = b1F[p + 2];
                    const uint32_t b0l = b2F[p], b1l = b2F[p + 2];
                    mma_s8(accH[mt][nt], a1F, b0h, b1h);
                    mma_s8(accM[mt][nt], a2F, b0h, b1h);
                    mma_s8(accM[mt][nt], a1F, b0l, b1l);
                }
            }
        }
    }

    const int g  = lane >> 2;
    const int tg = lane & 3;
    const float i256 = 0.00390625f;

    if (EPI == 1) {
        CP_WAIT0();
        __syncthreads();
        float* rmaxf = (float*)smem;
        if (tid < 128) rmaxf[tid] = 0.f;
        __syncthreads();
#pragma unroll
        for (int mt = 0; mt < 2; ++mt) {
            const int lrow = wm * 32 + mt * 16 + g;
            const int grow = by * 128 + lrow;
            const float sa0 = sA[grow], sa8 = sA[grow + 8];
            float am0 = 0.f, am1 = 0.f;
#pragma unroll
            for (int nt = 0; nt < 4; ++nt) {
                const int colg = bx * 128 + wn * 32 + nt * 8 + 2 * tg;
                const float sb0 = sB[colg], sb1 = sB[colg + 1];
                float v0 = sa0 * sb0 * ((float)accH[mt][nt][0] + (float)accM[mt][nt][0] * i256);
                float v1 = sa0 * sb1 * ((float)accH[mt][nt][1] + (float)accM[mt][nt][1] * i256);
                float v2 = sa8 * sb0 * ((float)accH[mt][nt][2] + (float)accM[mt][nt][2] * i256);
                float v3 = sa8 * sb1 * ((float)accH[mt][nt][3] + (float)accM[mt][nt][3] * i256);
                am0 = fmaxf(am0, fmaxf(fabsf(v0), fabsf(v1)));
                am1 = fmaxf(am1, fmaxf(fabsf(v2), fabsf(v3)));
            }
            atomicMax((unsigned int*)&rmaxf[lrow],     __float_as_uint(am0));
            atomicMax((unsigned int*)&rmaxf[lrow + 8], __float_as_uint(am1));
        }
        __syncthreads();
        const int seg = (bx < 16) ? bx : (bx - 16);
        int8_t* o1 = (bx < 16) ? oq1a : oq1b;
        int8_t* o2 = (bx < 16) ? oq2a : oq2b;
        float*  osc = (bx < 16) ? osca : oscb;
#pragma unroll
        for (int mt = 0; mt < 2; ++mt) {
            const int lrow = wm * 32 + mt * 16 + g;
            const size_t grow = (size_t)(by * 128 + lrow);
            const float sa0 = sA[grow], sa8 = sA[grow + 8];
            const float am0 = fmaxf(rmaxf[lrow], 1e-20f);
            const float am1 = fmaxf(rmaxf[lrow + 8], 1e-20f);
            const float inv0 = 127.0f / am0, inv1 = 127.0f / am1;
            if (wn == 0 && tg == 0) {
                osc[grow * 16 + seg]       = am0 * (1.0f / 127.0f);
                osc[(grow + 8) * 16 + seg] = am1 * (1.0f / 127.0f);
            }
#pragma unroll
            for (int nt = 0; nt < 4; ++nt) {
                const int colg = bx * 128 + wn * 32 + nt * 8 + 2 * tg;
                const int colo = seg * 128 + wn * 32 + nt * 8 + 2 * tg;
                const float sb0 = sB[colg], sb1 = sB[colg + 1];
                float v0 = sa0 * sb0 * ((float)accH[mt][nt][0] + (float)accM[mt][nt][0] * i256);
                float v1 = sa0 * sb1 * ((float)accH[mt][nt][1] + (float)accM[mt][nt][1] * i256);
                float v2 = sa8 * sb0 * ((float)accH[mt][nt][2] + (float)accM[mt][nt][2] * i256);
                float v3 = sa8 * sb1 * ((float)accH[mt][nt][3] + (float)accM[mt][nt][3] * i256);
                int8_t h0, l0, h1, l1;
                quant2(v0, inv0, h0, l0); quant2(v1, inv0, h1, l1);
                *(char2*)(o1 + grow * D_DIM + colo) = make_char2(h0, h1);
                *(char2*)(o2 + grow * D_DIM + colo) = make_char2(l0, l1);
                quant2(v2, inv1, h0, l0); quant2(v3, inv1, h1, l1);
                *(char2*)(o1 + (grow + 8) * D_DIM + colo) = make_char2(h0, h1);
                *(char2*)(o2 + (grow + 8) * D_DIM + colo) = make_char2(l0, l1);
            }
        }
        return;
    }

#pragma unroll
    for (int mt = 0; mt < 2; ++mt) {
        const int row = by * 128 + wm * 32 + mt * 16 + g;
        const float sa0 = sA[row], sa8 = sA[row + 8];
        float rm0 = 0.f, rm1 = 0.f;
#pragma unroll
        for (int nt = 0; nt < 4; ++nt) {
            const int col = bx * 128 + wn * 32 + nt * 8 + 2 * tg;
            const float sb0 = sB[col], sb1 = sB[col + 1];
            float v0 = sa0 * sb0 * ((float)accH[mt][nt][0] + (float)accM[mt][nt][0] * i256);
            float v1 = sa0 * sb1 * ((float)accH[mt][nt][1] + (float)accM[mt][nt][1] * i256);
            float v2 = sa8 * sb0 * ((float)accH[mt][nt][2] + (float)accM[mt][nt][2] * i256);
            float v3 = sa8 * sb1 * ((float)accH[mt][nt][3] + (float)accM[mt][nt][3] * i256);
            if (EPI == 2) {
                *(__nv_bfloat162*)(Obf + (size_t)row * Nd + col) =
                    __nv_bfloat162(__float2bfloat16_rn(v0), __float2bfloat16_rn(v1));
                *(__nv_bfloat162*)(Obf + (size_t)(row + 8) * Nd + col) =
                    __nv_bfloat162(__float2bfloat16_rn(v2), __float2bfloat16_rn(v3));
            } else {
                if (HAS_BIAS) {
                    float2 b2v = *(const float2*)(bias + col);
                    v0 += b2v.x; v1 += b2v.y; v2 += b2v.x; v3 += b2v.y;
                }
                if (RELU) {
                    v0 = fmaxf(v0, 0.f); v1 = fmaxf(v1, 0.f);
                    v2 = fmaxf(v2, 0.f); v3 = fmaxf(v3, 0.f);
                }
                if (HAS_RES) {
                    float2 ra = *(const float2*)(res + (size_t)row * Nd + col);
                    float2 rb = *(const float2*)(res + (size_t)(row + 8) * Nd + col);
                    v0 += ra.x; v1 += ra.y; v2 += rb.x; v3 += rb.y;
                }
                if (ROWMAX) {
                    rm0 = fmaxf(rm0, fmaxf(fabsf(v0), fabsf(v1)));
                    rm1 = fmaxf(rm1, fmaxf(fabsf(v2), fabsf(v3)));
                }
                *(float2*)(Cf + (size_t)row * Nd + col)       = make_float2(v0, v1);
                *(float2*)(Cf + (size_t)(row + 8) * Nd + col) = make_float2(v2, v3);
            }
        }
        if (EPI == 0 && ROWMAX) {
            rm0 = fmaxf(rm0, __shfl_xor_sync(0xffffffffu, rm0, 1));
            rm0 = fmaxf(rm0, __shfl_xor_sync(0xffffffffu, rm0, 2));
            rm1 = fmaxf(rm1, __shfl_xor_sync(0xffffffffu, rm1, 1));
            rm1 = fmaxf(rm1, __shfl_xor_sync(0xffffffffu, rm1, 2));
            if (tg == 0) {
                atomicMax((unsigned int*)&rowmax[row],     __float_as_uint(rm0));
                atomicMax((unsigned int*)&rowmax[row + 8], __float_as_uint(rm1));
            }
        }
    }
#undef ISSUE_I8
}

// ===========================================================================
// Tensor-core flash attention (QUIRK layout); heavy-first CTA scheduling.
// ===========================================================================
#define AQ_H  0
#define AQ_L  18432
#define AK_H(bf) (36864 + (bf) * 18432)
#define AK_L(bf) (AK_H(bf) + 9216)
#define AVT(bf)  (73728 + (bf) * 18432)
#define APS_H 110592
#define APS_L 129024
#define ASQ   147456
#define ASK(bf) (147968 + (bf) * 256)
#define ATT_SMEM 148480

__global__ __launch_bounds__(256)
void attn_i8(const int8_t* __restrict__ Qq1, const int8_t* __restrict__ Qq2,
             const float* __restrict__ Qs,
             const int8_t* __restrict__ Kq1, const int8_t* __restrict__ Kq2,
             const float* __restrict__ Ks,
             const bf16* __restrict__ VT, float* __restrict__ O,
             float* __restrict__ rowmax)
{
    extern __shared__ char smem[];
    const uint32_t sb = smem_u32(smem);
    float* sQf = (float*)(smem + ASQ);
    const int qt   = (int)gridDim.x - 1 - (int)blockIdx.x;   // heavy CTAs first
    const int head = blockIdx.y;
    const int b    = blockIdx.z;
    const int tid  = threadIdx.x;
    const int warp = tid >> 5;
    const int lane = tid & 31;
    const int l15  = lane & 15;
    const int lhalf = lane >> 4;
    const int g  = lane >> 2;
    const int tg = lane & 3;
    const int mrow = warp * 16;
    const int ntiles = 2 * qt + 2;
    const int bh = b * NH + head;
    const size_t hbase = (size_t)bh * S_LEN * HD;
    const int i0 = qt * 128;
    const bf16* vth = VT + (size_t)bh * HD * S_LEN;

    if (tid < 128) sQf[tid] = Qs[(size_t)bh * S_LEN + i0 + tid];

#pragma unroll
    for (int i = 0; i < 4; ++i) {
        int id = tid + 256 * i;
        int r = id >> 3, c = (id & 7) * 16;
        cpa16(sb + AQ_H + r * 144 + c, Qq1 + hbase + (size_t)(i0 + r) * HD + c);
        cpa16(sb + AQ_L + r * 144 + c, Qq2 + hbase + (size_t)(i0 + r) * HD + c);
    }

#define ATT_ISSUE(bf_, jt_) do { \
    const size_t kj0_ = (size_t)(jt_) * 64; \
    for (int i_ = tid; i_ < 512; i_ += 256) { \
        int r_ = i_ >> 3, c_ = (i_ & 7) * 16; \
        cpa16(sb + AK_H(bf_) + r_ * 144 + c_, Kq1 + hbase + (kj0_ + r_) * HD + c_); \
        cpa16(sb + AK_L(bf_) + r_ * 144 + c_, Kq2 + hbase + (kj0_ + r_) * HD + c_); \
    } \
    for (int i_ = tid; i_ < 1024; i_ += 256) { \
        int r_ = i_ >> 3, c_ = (i_ & 7) * 16; \
        cpa16(sb + AVT(bf_) + r_ * 144 + c_, \
              (const char*)(vth + (size_t)r_ * S_LEN + kj0_) + c_); \
    } \
    if (tid < 64) ((float*)(smem + ASK(bf_)))[tid] = Ks[(size_t)bh * S_LEN + kj0_ + tid]; \
} while (0)

    ATT_ISSUE(0, 0); CP_COMMIT();
    ATT_ISSUE(1, 1); CP_COMMIT();

    float o_acc[16][4];
#pragma unroll
    for (int ot = 0; ot < 16; ++ot)
#pragma unroll
        for (int e = 0; e < 4; ++e) o_acc[ot][e] = 0.f;
    float m0 = -1e30f, m1 = -1e30f, l0 = 0.f, l1 = 0.f;
    const float inv_sqrt_d = 0.08838834764831845f;
    const float inv256 = 0.00390625f;
    const int i_g0 = i0 + mrow + g;
    const int i_g1 = i_g0 + 8;

    const uint32_t qbH = sb + AQ_H + (mrow + l15) * 144 + lhalf * 16;
    const uint32_t qbL = sb + AQ_L + (mrow + l15) * 144 + lhalf * 16;
    const uint32_t pbH = sb + APS_H + (mrow + l15) * 144 + lhalf * 16;
    const uint32_t pbL = sb + APS_L + (mrow + l15) * 144 + lhalf * 16;

    for (int jt = 0; jt < ntiles; ++jt) {
        const int buf = jt & 1;
        CP_WAIT1();
        __syncthreads();
        const float* sKf = (const float*)(smem + ASK(buf));

        int accH[8][4], accM[8][4];
#pragma unroll
        for (int nt = 0; nt < 8; ++nt)
#pragma unroll
            for (int e = 0; e < 4; ++e) { accH[nt][e] = 0; accM[nt][e] = 0; }

#pragma unroll
        for (int ks = 0; ks < 4; ++ks) {
            uint32_t aH[4], aL[4];
            ldmx4(aH, qbH + ks * 32);
            ldmx4(aL, qbL + ks * 32);
#pragma unroll
            for (int ng = 0; ng < 4; ++ng) {
                uint32_t bH4[4], bL4[4];
                const uint32_t kaddr = (uint32_t)((ng * 16 + l15) * 144) + lhalf * 16 + ks * 32;
                ldmx4(bH4, sb + AK_H(buf) + kaddr);
                ldmx4(bL4, sb + AK_L(buf) + kaddr);
                mma_s8(accH[2 * ng],     aH, bH4[0], bH4[2]);
                mma_s8(accM[2 * ng],     aL, bH4[0], bH4[2]);
                mma_s8(accM[2 * ng],     aH, bL4[0], bL4[2]);
                mma_s8(accH[2 * ng + 1], aH, bH4[1], bH4[3]);
                mma_s8(accM[2 * ng + 1], aL, bH4[1], bH4[3]);
                mma_s8(accM[2 * ng + 1], aH, bL4[1], bL4[3]);
            }
        }

        const float sq0 = sQf[mrow + g], sq1 = sQf[mrow + g + 8];
        const bool diag = (jt >= 2 * qt);
        float sv[8][4];
        float rm0 = -1e30f, rm1 = -1e30f;
#pragma unroll
        for (int nt = 0; nt < 8; ++nt) {
            const int col0 = nt * 8 + 2 * tg;
            const float sk0 = sKf[col0], sk1 = sKf[col0 + 1];
            float s00 = sq0 * sk0 * ((float)accH[nt][0] + (float)accM[nt][0] * inv256);
            float s01 = sq0 * sk1 * ((float)accH[nt][1] + (float)accM[nt][1] * inv256);
            float s10 = sq1 * sk0 * ((float)accH[nt][2] + (float)accM[nt][2] * inv256);
            float s11 = sq1 * sk1 * ((float)accH[nt][3] + (float)accM[nt][3] * inv256);
            if (diag) {
                const int j0g = jt * 64 + col0;
                if (j0g     > i_g0) s00 = -1e9f;
                if (j0g + 1 > i_g0) s01 = -1e9f;
                if (j0g     > i_g1) s10 = -1e9f;
                if (j0g + 1 > i_g1) s11 = -1e9f;
            }
            s00 *= inv_sqrt_d; s01 *= inv_sqrt_d; s10 *= inv_sqrt_d; s11 *= inv_sqrt_d;
            sv[nt][0] = s00; sv[nt][1] = s01; sv[nt][2] = s10; sv[nt][3] = s11;
            rm0 = fmaxf(rm0, fmaxf(s00, s01));
            rm1 = fmaxf(rm1, fmaxf(s10, s11));
        }
        rm0 = fmaxf(rm0, __shfl_xor_sync(0xffffffffu, rm0, 1));
        rm0 = fmaxf(rm0, __shfl_xor_sync(0xffffffffu, rm0, 2));
        rm1 = fmaxf(rm1, __shfl_xor_sync(0xffffffffu, rm1, 1));
        rm1 = fmaxf(rm1, __shfl_xor_sync(0xffffffffu, rm1, 2));
        const float mn0 = fmaxf(m0, rm0), mn1 = fmaxf(m1, rm1);
        const float cr0 = __expf(m0 - mn0), cr1 = __expf(m1 - mn1);
        m0 = mn0; m1 = mn1;
        float rs0 = 0.f, rs1 = 0.f;
#pragma unroll
        for (int nt = 0; nt < 8; ++nt) {
            float p00 = __expf(sv[nt][0] - mn0);
            float p01 = __expf(sv[nt][1] - mn0);
            float p10 = __expf(sv[nt][2] - mn1);
            float p11 = __expf(sv[nt][3] - mn1);
            rs0 += p00 + p01; rs1 += p10 + p11;
            bf16 h00 = __float2bfloat16_rn(p00), h01 = __float2bfloat16_rn(p01);
            bf16 h10 = __float2bfloat16_rn(p10), h11 = __float2bfloat16_rn(p11);
            bf16 l00b = __float2bfloat16_rn(p00 - __bfloat162float(h00));
            bf16 l01b = __float2bfloat16_rn(p01 - __bfloat162float(h01));
            bf16 l10b = __float2bfloat16_rn(p10 - __bfloat162float(h10));
            bf16 l11b = __float2bfloat16_rn(p11 - __bfloat162float(h11));
            const uint32_t cofs = (uint32_t)((nt * 8 + 2 * tg) * 2);
            *(__nv_bfloat162*)(smem + APS_H + (mrow + g) * 144 + cofs)     = __nv_bfloat162(h00, h01);
            *(__nv_bfloat162*)(smem + APS_H + (mrow + g + 8) * 144 + cofs) = __nv_bfloat162(h10, h11);
            *(__nv_bfloat162*)(smem + APS_L + (mrow + g) * 144 + cofs)     = __nv_bfloat162(l00b, l01b);
            *(__nv_bfloat162*)(smem + APS_L + (mrow + g + 8) * 144 + cofs) = __nv_bfloat162(l10b, l11b);
        }
        rs0 += __shfl_xor_sync(0xffffffffu, rs0, 1);
        rs0 += __shfl_xor_sync(0xffffffffu, rs0, 2);
        rs1 += __shfl_xor_sync(0xffffffffu, rs1, 1);
        rs1 += __shfl_xor_sync(0xffffffffu, rs1, 2);
        l0 = l0 * cr0 + rs0;
        l1 = l1 * cr1 + rs1;
#pragma unroll
        for (int ot = 0; ot < 16; ++ot) {
            o_acc[ot][0] *= cr0; o_acc[ot][1] *= cr0;
            o_acc[ot][2] *= cr1; o_acc[ot][3] *= cr1;
        }
        __syncwarp();

#pragma unroll
        for (int ks = 0; ks < 4; ++ks) {
            uint32_t aH[4], aL[4];
            ldmx4(aH, pbH + ks * 32);
            ldmx4(aL, pbL + ks * 32);
#pragma unroll
            for (int vg = 0; vg < 8; ++vg) {
                uint32_t vb[4];
                ldmx4(vb, sb + AVT(buf) + (uint32_t)((vg * 16 + l15) * 144) + lhalf * 16 + ks * 32);
                mma_bf16(o_acc[2 * vg],     aH, vb[0], vb[2]);
                mma_bf16(o_acc[2 * vg],     aL, vb[0], vb[2]);
                mma_bf16(o_acc[2 * vg + 1], aH, vb[1], vb[3]);
                mma_bf16(o_acc[2 * vg + 1], aL, vb[1], vb[3]);
            }
        }
        __syncthreads();
        if (jt + 2 < ntiles) { ATT_ISSUE(buf, jt + 2); }
        CP_COMMIT();
    }

    const float li0 = 1.0f / l0, li1 = 1.0f / l1;
    const size_t grow0 = (size_t)b * S_LEN + i0 + mrow + g;
    float* orow0 = O + grow0       * D_DIM + head * HD;
    float* orow1 = O + (grow0 + 8) * D_DIM + head * HD;
    float am0 = 0.f, am1 = 0.f;
#pragma unroll
    for (int ot = 0; ot < 16; ++ot) {
        const int col = ot * 8 + 2 * tg;
        float a0 = o_acc[ot][0] * li0, a1 = o_acc[ot][1] * li0;
        float a2 = o_acc[ot][2] * li1, a3 = o_acc[ot][3] * li1;
        am0 = fmaxf(am0, fmaxf(fabsf(a0), fabsf(a1)));
        am1 = fmaxf(am1, fmaxf(fabsf(a2), fabsf(a3)));
        *(float2*)(orow0 + col) = make_float2(a0, a1);
        *(float2*)(orow1 + col) = make_float2(a2, a3);
    }
    am0 = fmaxf(am0, __shfl_xor_sync(0xffffffffu, am0, 1));
    am0 = fmaxf(am0, __shfl_xor_sync(0xffffffffu, am0, 2));
    am1 = fmaxf(am1, __shfl_xor_sync(0xffffffffu, am1, 1));
    am1 = fmaxf(am1, __shfl_xor_sync(0xffffffffu, am1, 2));
    if (tg == 0) {
        atomicMax((unsigned int*)&rowmax[grow0],     __float_as_uint(am0));
        atomicMax((unsigned int*)&rowmax[grow0 + 8], __float_as_uint(am1));
    }
#undef ATT_ISSUE
}

// ===========================================================================
// Launch
// ===========================================================================
extern "C" void kernel_launch(void* const* d_in, const int* in_sizes, int n_in,
                              void* d_out, int out_size)
{
    (void)in_sizes; (void)n_in; (void)out_size;
    const float* x    = (const float*)d_in[0];
    const float* Wq   = (const float*)d_in[2];
    const float* Wk   = (const float*)d_in[3];
    const float* Wv   = (const float*)d_in[4];
    const float* Wo   = (const float*)d_in[5];
    const float* ln1g = (const float*)d_in[6];
    const float* ln1b = (const float*)d_in[7];
    const float* W1   = (const float*)d_in[8];
    const float* b1   = (const float*)d_in[9];
    const float* W2   = (const float*)d_in[10];
    const float* b2   = (const float*)d_in[11];
    const float* ln2g = (const float*)d_in[12];
    const float* ln2b = (const float*)d_in[13];
    float* out = (float*)d_out;

    int8_t *hq1, *hq2, *atq1, *atq2, *ffq1, *ffq2;
    float *hs, *ats, *ffs, *atrm, *ffrm;
    float *attn, *x2, *ff;
    int8_t *qq1, *qq2, *kq1, *kq2;
    float *qsc, *ksc;
    bf16 *vbf, *vt;
    int8_t *wqkq1, *wqkq2, *wvq1, *wvq2, *woq1, *woq2, *w1q1, *w1q2, *w2q1, *w2q2;
    float *wqks, *wqam, *wkam, *wvam, *wvs, *woam, *wos, *w1am, *w1s, *w2am, *w2s;
    cudaGetSymbolAddress((void**)&hq1,  g_h_q1);
    cudaGetSymbolAddress((void**)&hq2,  g_h_q2);
    cudaGetSymbolAddress((void**)&hs,   g_h_s);
    cudaGetSymbolAddress((void**)&attn, g_attn);
    cudaGetSymbolAddress((void**)&atq1, g_at_q1);
    cudaGetSymbolAddress((void**)&atq2, g_at_q2);
    cudaGetSymbolAddress((void**)&ats,  g_at_s);
    cudaGetSymbolAddress((void**)&atrm, g_at_rm);
    cudaGetSymbolAddress((void**)&x2,   g_x2);
    cudaGetSymbolAddress((void**)&ff,   g_ff);
    cudaGetSymbolAddress((void**)&ffq1, g_ff_q1);
    cudaGetSymbolAddress((void**)&ffq2, g_ff_q2);
    cudaGetSymbolAddress((void**)&ffs,  g_ff_s);
    cudaGetSymbolAddress((void**)&ffrm, g_ff_rm);
    cudaGetSymbolAddress((void**)&qq1,  g_q_q1);
    cudaGetSymbolAddress((void**)&qq2,  g_q_q2);
    cudaGetSymbolAddress((void**)&qsc,  g_q_sc);
    cudaGetSymbolAddress((void**)&kq1,  g_k_q1);
    cudaGetSymbolAddress((void**)&kq2,  g_k_q2);
    cudaGetSymbolAddress((void**)&ksc,  g_k_sc);
    cudaGetSymbolAddress((void**)&vbf,  g_vbf);
    cudaGetSymbolAddress((void**)&vt,   g_vt);
    cudaGetSymbolAddress((void**)&wqkq1, g_wqk_q1);
    cudaGetSymbolAddress((void**)&wqkq2, g_wqk_q2);
    cudaGetSymbolAddress((void**)&wqks,  g_wqk_s);
    cudaGetSymbolAddress((void**)&wqam,  g_wq_am);
    cudaGetSymbolAddress((void**)&wkam,  g_wk_am);
    cudaGetSymbolAddress((void**)&wvq1, g_wv_q1);
    cudaGetSymbolAddress((void**)&wvq2, g_wv_q2);
    cudaGetSymbolAddress((void**)&wvam, g_wv_am);
    cudaGetSymbolAddress((void**)&wvs,  g_wv_s);
    cudaGetSymbolAddress((void**)&woq1, g_wo_q1);
    cudaGetSymbolAddress((void**)&woq2, g_wo_q2);
    cudaGetSymbolAddress((void**)&woam, g_wo_am);
    cudaGetSymbolAddress((void**)&wos,  g_wo_s);
    cudaGetSymbolAddress((void**)&w1q1, g_w1_q1);
    cudaGetSymbolAddress((void**)&w1q2, g_w1_q2);
    cudaGetSymbolAddress((void**)&w1am, g_w1_am);
    cudaGetSymbolAddress((void**)&w1s,  g_w1_s);
    cudaGetSymbolAddress((void**)&w2q1, g_w2_q1);
    cudaGetSymbolAddress((void**)&w2q2, g_w2_q2);
    cudaGetSymbolAddress((void**)&w2am, g_w2_am);
    cudaGetSymbolAddress((void**)&w2s,  g_w2_s);

    cudaFuncSetAttribute(attn_i8,
                         cudaFuncAttributeMaxDynamicSharedMemorySize, ATT_SMEM);
    cudaFuncSetAttribute(gemm_i8<0, false, false, true, false>,
                         cudaFuncAttributeMaxDynamicSharedMemorySize, I8_SMEM);
    cudaFuncSetAttribute(gemm_i8<0, true, true, false, true>,
                         cudaFuncAttributeMaxDynamicSharedMemorySize, I8_SMEM);
    cudaFuncSetAttribute(gemm_i8<0, false, true, true, false>,
                         cudaFuncAttributeMaxDynamicSharedMemorySize, I8_SMEM);
    cudaFuncSetAttribute(gemm_i8<1, false, false, false, false>,
                         cudaFuncAttributeMaxDynamicSharedMemorySize, I8_SMEM);
    cudaFuncSetAttribute(gemm_i8<2, false, false, false, false>,
                         cudaFuncAttributeMaxDynamicSharedMemorySize, I8_SMEM);

    const dim3 blk(256);
    const dim3 blkG(512);

    // ---- weight prep (two-pass, high-parallelism; proven round-14 shape) ----
    cudaMemsetAsync(wqam, 0, D_DIM * sizeof(float));
    cudaMemsetAsync(wkam, 0, D_DIM * sizeof(float));
    cudaMemsetAsync(wvam, 0, D_DIM * sizeof(float));
    cudaMemsetAsync(woam, 0, D_DIM * sizeof(float));
    cudaMemsetAsync(w1am, 0, M_FF * sizeof(float));
    cudaMemsetAsync(w2am, 0, D_DIM * sizeof(float));
    cudaMemsetAsync(atrm, 0, ROWS * sizeof(float));
    cudaMemsetAsync(ffrm, 0, ROWS * sizeof(float));
    colamax_kernel<<<dim3(64, 64),  blk>>>(Wq, D_DIM, D_DIM, wqam);
    colamax_kernel<<<dim3(64, 64),  blk>>>(Wk, D_DIM, D_DIM, wkam);
    colamax_kernel<<<dim3(64, 64),  blk>>>(Wv, D_DIM, D_DIM, wvam);
    colamax_kernel<<<dim3(64, 64),  blk>>>(Wo, D_DIM, D_DIM, woam);
    colamax_kernel<<<dim3(M_FF / 32,  D_DIM / 32), blk>>>(W1, D_DIM, M_FF, w1am);
    colamax_kernel<<<dim3(D_DIM / 32, M_FF / 32),  blk>>>(W2, M_FF, D_DIM, w2am);
    transpose_quant_i8<<<dim3(64, 64),  blk>>>(Wq, wqam, wqkq1, wqkq2, wqks, D_DIM, D_DIM);
    transpose_quant_i8<<<dim3(64, 64),  blk>>>(Wk, wkam,
        wqkq1 + (size_t)D_DIM * D_DIM, wqkq2 + (size_t)D_DIM * D_DIM,
        wqks + D_DIM, D_DIM, D_DIM);
    transpose_quant_i8<<<dim3(64, 64),  blk>>>(Wv, wvam, wvq1, wvq2, wvs, D_DIM, D_DIM);
    transpose_quant_i8<<<dim3(64, 64),  blk>>>(Wo, woam, woq1, woq2, wos, D_DIM, D_DIM);
    transpose_quant_i8<<<dim3(256, 64), blk>>>(W1, w1am, w1q1, w1q2, w1s, D_DIM, M_FF);
    transpose_quant_i8<<<dim3(64, 256), blk>>>(W2, w2am, w2q1, w2q2, w2s, M_FF, D_DIM);

    const dim3 gQK(32, 32);
    const dim3 gDD(D_DIM / 128, ROWS / 128);
    const dim3 gDM(M_FF / 128,  ROWS / 128);

    // ---- layer ----
    ln_quant_i8<<<ROWS, blk>>>(x, ln1g, ln1b, hq1, hq2, hs);
    gemm_i8<1, false, false, false, false><<<gQK, blkG, I8_SMEM>>>(
        hq1, hq2, wqkq1, wqkq2, hs, wqks, nullptr, nullptr, nullptr, nullptr, nullptr,
        qq1, qq2, qsc, kq1, kq2, ksc, 2 * D_DIM, D_DIM);
    gemm_i8<2, false, false, false, false><<<gDD, blkG, I8_SMEM>>>(
        hq1, hq2, wvq1, wvq2, hs, wvs, nullptr, nullptr, nullptr, vbf, nullptr,
        nullptr, nullptr, nullptr, nullptr, nullptr, nullptr, D_DIM, D_DIM);
    vt_split<<<dim3(S_LEN / 32, HD / 32, B_SZ * NH), blk>>>(vbf, vt);
    attn_i8<<<dim3(S_LEN / 128, NH, B_SZ), blk, ATT_SMEM>>>(
        qq1, qq2, qsc, kq1, kq2, ksc, vt, attn, atrm);
    rowquant_pre<<<ROWS, blk>>>(attn, D_DIM, atrm, atq1, atq2, ats);
    gemm_i8<0, false, false, true, false><<<gDD, blkG, I8_SMEM>>>(
        atq1, atq2, woq1, woq2, ats, wos, nullptr, x, x2, nullptr, nullptr,
        nullptr, nullptr, nullptr, nullptr, nullptr, nullptr, D_DIM, D_DIM);
    ln_quant_i8<<<ROWS, blk>>>(x2, ln2g, ln2b, hq1, hq2, hs);
    gemm_i8<0, true, true, false, true><<<gDM, blkG, I8_SMEM>>>(
        hq1, hq2, w1q1, w1q2, hs, w1s, b1, nullptr, ff, nullptr, ffrm,
        nullptr, nullptr, nullptr, nullptr, nullptr, nullptr, M_FF, D_DIM);
    rowquant_pre<<<ROWS, blk>>>(ff, M_FF, ffrm, ffq1, ffq2, ffs);
    gemm_i8<0, false, true, true, false><<<gDD, blkG, I8_SMEM>>>(
        ffq1, ffq2, w2q1, w2q2, ffs, w2s, b2, x2, out, nullptr, nullptr,
        nullptr, nullptr, nullptr, nullptr, nullptr, nullptr, D_DIM, M_FF);
}

// round 17
// speedup vs baseline: 1.1467x; 1.0080x over previous
#include <cuda_runtime.h>
#include <cuda_bf16.h>
#include <cstdint>
#include <math.h>

// Problem constants
#define S_LEN 2048
#define D_DIM 2048
#define B_SZ  2
#define NH    16
#define HD    128
#define M_FF  8192
#define ROWS  (B_SZ * S_LEN)   // 4096

typedef __nv_bfloat16 bf16;

// -------------------- scratch (device globals; no allocation allowed) -----
__device__ __align__(16) int8_t g_h_q1  [ROWS * D_DIM];
__device__ __align__(16) int8_t g_h_q2  [ROWS * D_DIM];
__device__            float  g_h_s   [ROWS];
__device__ __align__(16) float g_attn  [ROWS * D_DIM];
__device__ __align__(16) int8_t g_at_q1 [ROWS * D_DIM];
__device__ __align__(16) int8_t g_at_q2 [ROWS * D_DIM];
__device__            float  g_at_s  [ROWS];
__device__            float  g_at_rm [ROWS];
__device__ __align__(16) float g_x2    [ROWS * D_DIM];
__device__ __align__(16) float g_ff    [ROWS * M_FF];
__device__ __align__(16) int8_t g_ff_q1 [ROWS * M_FF];
__device__ __align__(16) int8_t g_ff_q2 [ROWS * M_FF];
__device__            float  g_ff_s  [ROWS];
__device__            float  g_ff_rm [ROWS];
// attention operands (flat quirk layout; scales at [row*16+seg] == [bh*S+j])
__device__ __align__(16) int8_t g_q_q1  [ROWS * D_DIM];
__device__ __align__(16) int8_t g_q_q2  [ROWS * D_DIM];
__device__            float  g_q_sc  [ROWS * NH];
__device__ __align__(16) int8_t g_k_q1  [ROWS * D_DIM];
__device__ __align__(16) int8_t g_k_q2  [ROWS * D_DIM];
__device__            float  g_k_sc  [ROWS * NH];
__device__ __align__(16) bf16  g_vbf   [ROWS * D_DIM];
__device__ __align__(16) bf16  g_vt    [B_SZ * NH * HD * S_LEN];
// int8 2-limb weights ([N][K]); Wq+Wk stacked
__device__ __align__(16) int8_t g_wqk_q1 [2 * D_DIM * D_DIM];
__device__ __align__(16) int8_t g_wqk_q2 [2 * D_DIM * D_DIM];
__device__            float  g_wqk_s  [2 * D_DIM];
__device__            float  g_wq_am [D_DIM];
__device__            float  g_wk_am [D_DIM];
__device__ __align__(16) int8_t g_wv_q1 [D_DIM * D_DIM];
__device__ __align__(16) int8_t g_wv_q2 [D_DIM * D_DIM];
__device__            float  g_wv_am [D_DIM];
__device__            float  g_wv_s  [D_DIM];
__device__ __align__(16) int8_t g_wo_q1 [D_DIM * D_DIM];
__device__ __align__(16) int8_t g_wo_q2 [D_DIM * D_DIM];
__device__            float  g_wo_am [D_DIM];
__device__            float  g_wo_s  [D_DIM];
__device__ __align__(16) int8_t g_w1_q1 [M_FF * D_DIM];
__device__ __align__(16) int8_t g_w1_q2 [M_FF * D_DIM];
__device__            float  g_w1_am [M_FF];
__device__            float  g_w1_s  [M_FF];
__device__ __align__(16) int8_t g_w2_q1 [D_DIM * M_FF];
__device__ __align__(16) int8_t g_w2_q2 [D_DIM * M_FF];
__device__            float  g_w2_am [D_DIM];
__device__            float  g_w2_s  [D_DIM];

// -------------------- side stream + events (created at module load; no
// device-memory allocation involved; used identically on every call) -------
struct PrepStream {
    cudaStream_t s1;
    cudaEvent_t  e0, evV, evO, ev1, ev2;
    PrepStream() {
        cudaStreamCreateWithFlags(&s1, cudaStreamNonBlocking);
        cudaEventCreateWithFlags(&e0,  cudaEventDisableTiming);
        cudaEventCreateWithFlags(&evV, cudaEventDisableTiming);
        cudaEventCreateWithFlags(&evO, cudaEventDisableTiming);
        cudaEventCreateWithFlags(&ev1, cudaEventDisableTiming);
        cudaEventCreateWithFlags(&ev2, cudaEventDisableTiming);
    }
};
static PrepStream g_ps;

// ===========================================================================
// helpers
// ===========================================================================
__device__ __forceinline__ uint32_t smem_u32(const void* p) {
    uint32_t a;
    asm("{ .reg .u64 t; cvta.to.shared.u64 t, %1; cvt.u32.u64 %0, t; }" : "=r"(a) : "l"(p));
    return a;
}
__device__ __forceinline__ void cpa16(uint32_t dst, const void* src) {
    asm volatile("cp.async.cg.shared.global [%0], [%1], 16;" :: "r"(dst), "l"(src));
}
#define CP_COMMIT() asm volatile("cp.async.commit_group;" ::: "memory")
#define CP_WAIT1()  asm volatile("cp.async.wait_group 1;" ::: "memory")
#define CP_WAIT0()  asm volatile("cp.async.wait_group 0;" ::: "memory")

__device__ __forceinline__ void ldmx4(uint32_t* r, uint32_t addr) {
    asm volatile("ldmatrix.sync.aligned.m8n8.x4.shared.b16 {%0,%1,%2,%3}, [%4];"
        : "=r"(r[0]), "=r"(r[1]), "=r"(r[2]), "=r"(r[3]) : "r"(addr));
}
__device__ __forceinline__ void mma_bf16(float* d, const uint32_t* a, uint32_t b0, uint32_t b1) {
    asm volatile(
        "mma.sync.aligned.m16n8k16.row.col.f32.bf16.bf16.f32 "
        "{%0,%1,%2,%3},{%4,%5,%6,%7},{%8,%9},{%0,%1,%2,%3};"
        : "+f"(d[0]), "+f"(d[1]), "+f"(d[2]), "+f"(d[3])
        : "r"(a[0]), "r"(a[1]), "r"(a[2]), "r"(a[3]), "r"(b0), "r"(b1));
}
__device__ __forceinline__ void mma_s8(int* d, const uint32_t* a, uint32_t b0, uint32_t b1) {
    asm volatile(
        "mma.sync.aligned.m16n8k32.row.col.s32.s8.s8.s32 "
        "{%0,%1,%2,%3},{%4,%5,%6,%7},{%8,%9},{%0,%1,%2,%3};"
        : "+r"(d[0]), "+r"(d[1]), "+r"(d[2]), "+r"(d[3])
        : "r"(a[0]), "r"(a[1]), "r"(a[2]), "r"(a[3]), "r"(b0), "r"(b1));
}
__device__ __forceinline__ void quant2(float v, float inv_s, int8_t& h, int8_t& l) {
    float q  = v * inv_s;
    float q1 = rintf(q);
    float q2 = rintf((q - q1) * 256.0f);
    q2 = fminf(fmaxf(q2, -127.0f), 127.0f);
    h = (int8_t)(int)q1;
    l = (int8_t)(int)q2;
}

// ===========================================================================
// per-column absmax
// ===========================================================================
__global__ __launch_bounds__(256)
void colamax_kernel(const float* __restrict__ in, int R, int C, float* __restrict__ amax)
{
    __shared__ float sm_[8][33];
    const int tx = threadIdx.x & 31;
    const int ty = threadIdx.x >> 5;
    const int bx = blockIdx.x * 32, by = blockIdx.y * 32;
    float m = 0.f;
#pragma unroll
    for (int j = 0; j < 4; ++j)
        m = fmaxf(m, fabsf(in[(size_t)(by + ty + 8 * j) * C + bx + tx]));
    sm_[ty][tx] = m;
    __syncthreads();
    if (ty == 0) {
        float mm = sm_[0][tx];
#pragma unroll
        for (int r = 1; r < 8; ++r) mm = fmaxf(mm, sm_[r][tx]);
        atomicMax((unsigned int*)&amax[bx + tx], __float_as_uint(mm));
    }
}

// ===========================================================================
// transpose + int8 2-limb quant (weights)
// ===========================================================================
__global__ __launch_bounds__(256)
void transpose_quant_i8(const float* __restrict__ in, const float* __restrict__ amax,
                        int8_t* __restrict__ q1o, int8_t* __restrict__ q2o,
                        float* __restrict__ sOut, int R, int C)
{
    __shared__ float tile[32][33];
    const int tx = threadIdx.x & 31;
    const int ty = threadIdx.x >> 5;
    const int bx = blockIdx.x * 32, by = blockIdx.y * 32;
#pragma unroll
    for (int j = 0; j < 32; j += 8)
        tile[ty + j][tx] = in[(size_t)(by + ty + j) * C + bx + tx];
    __syncthreads();
#pragma unroll
    for (int j = 0; j < 32; j += 8) {
        const int orow = bx + ty + j;
        float am = fmaxf(amax[orow], 1e-20f);
        float s  = am * (1.0f / 127.0f);
        float inv = 127.0f / am;
        if (tx == 0) sOut[orow] = s;
        float v = tile[tx][ty + j];
        int8_t h, l; quant2(v, inv, h, l);
        size_t o = (size_t)orow * R + by + tx;
        q1o[o] = h; q2o[o] = l;
    }
}

// ===========================================================================
// quantize-only rowquant: uses precomputed row absmax
// ===========================================================================
__global__ __launch_bounds__(256)
void rowquant_pre(const float* __restrict__ in, int Kd, const float* __restrict__ rmax,
                  int8_t* __restrict__ q1, int8_t* __restrict__ q2, float* __restrict__ s)
{
    const int row = blockIdx.x;
    const int tid = threadIdx.x;
    const float mm = fmaxf(rmax[row], 1e-20f);
    if (tid == 0) s[row] = mm * (1.0f / 127.0f);
    const float inv = 127.0f / mm;
    const float* r = in + (size_t)row * Kd;
    for (int c = tid; c < Kd; c += 256) {
        int8_t h, l; quant2(r[c], inv, h, l);
        q1[(size_t)row * Kd + c] = h;
        q2[(size_t)row * Kd + c] = l;
    }
}

// ===========================================================================
// V^T split (bf16)
// ===========================================================================
__global__ __launch_bounds__(256)
void vt_split(const bf16* __restrict__ v, bf16* __restrict__ vt)
{
    __shared__ bf16 tile[32][34];
    const int tx = threadIdx.x & 31;
    const int ty = threadIdx.x >> 5;
    const int bh = blockIdx.z;
    const int j0 = blockIdx.x * 32, c0 = blockIdx.y * 32;
    const bf16* vb = v + (size_t)bh * S_LEN * HD;
#pragma unroll
    for (int jj = 0; jj < 32; jj += 8)
        tile[ty + jj][tx] = vb[(size_t)(j0 + ty + jj) * HD + c0 + tx];
    __syncthreads();
#pragma unroll
    for (int jj = 0; jj < 32; jj += 8)
        vt[((size_t)bh * HD + c0 + ty + jj) * S_LEN + j0 + tx] = tile[tx][ty + jj];
}

// ===========================================================================
// LayerNorm + int8 2-limb quant
// ===========================================================================
__global__ __launch_bounds__(256)
void ln_quant_i8(const float* __restrict__ x, const float* __restrict__ gam,
                 const float* __restrict__ bet, int8_t* __restrict__ q1,
                 int8_t* __restrict__ q2, float* __restrict__ sArr)
{
    __shared__ float red[9];
    const int row = blockIdx.x;
    const int tid = threadIdx.x;
    const float* xr = x + (size_t)row * D_DIM;

    float v[8];
    float sum = 0.f;
#pragma unroll
    for (int i = 0; i < 8; ++i) { v[i] = xr[tid + 256 * i]; sum += v[i]; }
#pragma unroll
    for (int d = 16; d > 0; d >>= 1) sum += __shfl_xor_sync(0xffffffffu, sum, d);
    if ((tid & 31) == 0) red[tid >> 5] = sum;
    __syncthreads();
    float tot = 0.f;
#pragma unroll
    for (int i = 0; i < 8; ++i) tot += red[i];
    const float mean = tot * (1.0f / (float)D_DIM);

    float s2 = 0.f;
#pragma unroll
    for (int i = 0; i < 8; ++i) { float d = v[i] - mean; s2 += d * d; }
    __syncthreads();
#pragma unroll
    for (int d = 16; d > 0; d >>= 1) s2 += __shfl_xor_sync(0xffffffffu, s2, d);
    if ((tid & 31) == 0) red[tid >> 5] = s2;
    __syncthreads();
    tot = 0.f;
#pragma unroll
    for (int i = 0; i < 8; ++i) tot += red[i];
    const float rstd = rsqrtf(tot * (1.0f / (float)D_DIM) + 1e-5f);

    float o[8];
    float am = 0.f;
#pragma unroll
    for (int i = 0; i < 8; ++i) {
        int c = tid + 256 * i;
        o[i] = (v[i] - mean) * rstd * gam[c] + bet[c];
        am = fmaxf(am, fabsf(o[i]));
    }
    __syncthreads();
#pragma unroll
    for (int d = 16; d > 0; d >>= 1) am = fmaxf(am, __shfl_xor_sync(0xffffffffu, am, d));
    if ((tid & 31) == 0) red[tid >> 5] = am;
    __syncthreads();
    if (tid == 0) {
        float mm = red[0];
#pragma unroll
        for (int i = 1; i < 8; ++i) mm = fmaxf(mm, red[i]);
        mm = fmaxf(mm, 1e-20f);
        red[8] = mm;
        sArr[row] = mm * (1.0f / 127.0f);
    }
    __syncthreads();
    const float inv = 127.0f / red[8];
#pragma unroll
    for (int i = 0; i < 8; ++i) {
        int c = tid + 256 * i;
        int8_t h, l; quant2(o[i], inv, h, l);
        q1[(size_t)row * D_DIM + c] = h;
        q2[(size_t)row * D_DIM + c] = l;
    }
}

// ===========================================================================
// int8 2-limb tensor-core GEMM — 512 threads / 16 warps, warp tile 32x32.
// BK=64, 3-stage cp.async (96KB). EPI: 0 fp32 (+bias/relu/res, opt ROWMAX),
// 1 QK quantizing epilogue, 2 bf16 out.
// ===========================================================================
#define ISTAGE 32768
#define ISM_A2 8192
#define ISM_B1 16384
#define ISM_B2 24576
#define I8_SMEM (3 * ISTAGE)

template<int EPI, bool RELU, bool HAS_BIAS, bool HAS_RES, bool ROWMAX>
__global__ __launch_bounds__(512, 1)
void gemm_i8(const int8_t* __restrict__ A1, const int8_t* __restrict__ A2,
             const int8_t* __restrict__ B1, const int8_t* __restrict__ B2,
             const float* __restrict__ sA, const float* __restrict__ sB,
             const float* __restrict__ bias, const float* __restrict__ res,
             float* __restrict__ Cf, bf16* __restrict__ Obf, float* __restrict__ rowmax,
             int8_t* __restrict__ oq1a, int8_t* __restrict__ oq2a, float* __restrict__ osca,
             int8_t* __restrict__ oq1b, int8_t* __restrict__ oq2b, float* __restrict__ oscb,
             int Nd, int Kd)
{
    extern __shared__ char smem[];
    const uint32_t sb = smem_u32(smem);
    const int tid  = threadIdx.x;
    const int warp = tid >> 5;
    const int lane = tid & 31;
    const int wm   = warp & 3;
    const int wn   = warp >> 2;
    const int bx = blockIdx.x, by = blockIdx.y;
    const int ktiles = Kd >> 6;

    const int r0 = tid >> 2;
    const int cc = tid & 3;
    const int pc = (cc + (r0 >> 1)) & 3;
    const size_t gA0 = (size_t)(by * 128 + r0) * Kd + cc * 16;
    const size_t gB0 = (size_t)(bx * 128 + r0) * Kd + cc * 16;
    const int8_t* pA1 = A1 + gA0;  const int8_t* pA2 = A2 + gA0;
    const int8_t* pB1 = B1 + gB0;  const int8_t* pB2 = B2 + gB0;
    const uint32_t dA0 = (uint32_t)(r0 * 64 + pc * 16);

#define ISSUE_I8(slot, u) do { \
    uint32_t s0_ = sb + (slot) * ISTAGE; int ko_ = (u) * 64; \
    cpa16(s0_ + dA0,          pA1 + ko_); \
    cpa16(s0_ + dA0 + ISM_A2, pA2 + ko_); \
    cpa16(s0_ + dA0 + ISM_B1, pB1 + ko_); \
    cpa16(s0_ + dA0 + ISM_B2, pB2 + ko_); \
} while (0)

    const int l15   = lane & 15;
    const int chalf = lane >> 4;
    const uint32_t pc0 = (uint32_t)((chalf + (l15 >> 1)) & 3);
    const uint32_t pc1 = (uint32_t)((2 + chalf + (l15 >> 1)) & 3);
    const uint32_t offA[2] = { (uint32_t)((wm * 32 + l15) * 64) + pc0 * 16,
                               (uint32_t)((wm * 32 + l15) * 64) + pc1 * 16 };
    const uint32_t offB0[2] = { (uint32_t)((wn * 32 + l15) * 64) + pc0 * 16,
                                (uint32_t)((wn * 32 + l15) * 64) + pc1 * 16 };
    const uint32_t offB1[2] = { (uint32_t)((wn * 32 + 16 + l15) * 64) + pc0 * 16,
                                (uint32_t)((wn * 32 + 16 + l15) * 64) + pc1 * 16 };

    int accH[2][4][4], accM[2][4][4];
#pragma unroll
    for (int mt = 0; mt < 2; ++mt)
#pragma unroll
        for (int nt = 0; nt < 4; ++nt)
#pragma unroll
            for (int e = 0; e < 4; ++e) { accH[mt][nt][e] = 0; accM[mt][nt][e] = 0; }

    ISSUE_I8(0, 0); CP_COMMIT();
    ISSUE_I8(1, 1); CP_COMMIT();

    for (int t = 0; t < ktiles; ++t) {
        CP_WAIT1();
        __syncthreads();
        {
            const int u = t + 2;
            if (u < ktiles) { ISSUE_I8(u % 3, u); }
            CP_COMMIT();
        }
        const uint32_t st = sb + (t % 3) * ISTAGE;
#pragma unroll
        for (int j = 0; j < 2; ++j) {
            uint32_t b1F[8], b2F[8];
            ldmx4(&b1F[0], st + ISM_B1 + offB0[j]);
            ldmx4(&b1F[4], st + ISM_B1 + offB1[j]);
            ldmx4(&b2F[0], st + ISM_B2 + offB0[j]);
            ldmx4(&b2F[4], st + ISM_B2 + offB1[j]);
#pragma unroll
            for (int mt = 0; mt < 2; ++mt) {
                uint32_t a1F[4], a2F[4];
                ldmx4(a1F, st + mt * 1024 + offA[j]);
                ldmx4(a2F, st + ISM_A2 + mt * 1024 + offA[j]);
#pragma unroll
                for (int nt = 0; nt < 4; ++nt) {
                    const int p = (nt >> 1) * 4 + (nt & 1);
                    const uint32_t b0h = b1F[p], b1h = b1F[p + 2];
                    const uint32_t b0l = b2F[p], b1l = b2F[p + 2];
                    mma_s8(accH[mt][nt], a1F, b0h, b1h);
                    mma_s8(accM[mt][nt], a2F, b0h, b1h);
                    mma_s8(accM[mt][nt], a1F, b0l, b1l);
                }
            }
        }
    }

    const int g  = lane >> 2;
    const int tg = lane & 3;
    const float i256 = 0.00390625f;

    if (EPI == 1) {
        CP_WAIT0();
        __syncthreads();
        float* rmaxf = (float*)smem;
        if (tid < 128) rmaxf[tid] = 0.f;
        __syncthreads();
#pragma unroll
        for (int mt = 0; mt < 2; ++mt) {
            const int lrow = wm * 32 + mt * 16 + g;
            const int grow = by * 128 + lrow;
            const float sa0 = sA[grow], sa8 = sA[grow + 8];
            float am0 = 0.f, am1 = 0.f;
#pragma unroll
            for (int nt = 0; nt < 4; ++nt) {
                const int colg = bx * 128 + wn * 32 + nt * 8 + 2 * tg;
                const float sb0 = sB[colg], sb1 = sB[colg + 1];
                float v0 = sa0 * sb0 * ((float)accH[mt][nt][0] + (float)accM[mt][nt][0] * i256);
                float v1 = sa0 * sb1 * ((float)accH[mt][nt][1] + (float)accM[mt][nt][1] * i256);
                float v2 = sa8 * sb0 * ((float)accH[mt][nt][2] + (float)accM[mt][nt][2] * i256);
                float v3 = sa8 * sb1 * ((float)accH[mt][nt][3] + (float)accM[mt][nt][3] * i256);
                am0 = fmaxf(am0, fmaxf(fabsf(v0), fabsf(v1)));
                am1 = fmaxf(am1, fmaxf(fabsf(v2), fabsf(v3)));
            }
            atomicMax((unsigned int*)&rmaxf[lrow],     __float_as_uint(am0));
            atomicMax((unsigned int*)&rmaxf[lrow + 8], __float_as_uint(am1));
        }
        __syncthreads();
        const int seg = (bx < 16) ? bx : (bx - 16);
        int8_t* o1 = (bx < 16) ? oq1a : oq1b;
        int8_t* o2 = (bx < 16) ? oq2a : oq2b;
        float*  osc = (bx < 16) ? osca : oscb;
#pragma unroll
        for (int mt = 0; mt < 2; ++mt) {
            const int lrow = wm * 32 + mt * 16 + g;
            const size_t grow = (size_t)(by * 128 + lrow);
            const float sa0 = sA[grow], sa8 = sA[grow + 8];
            const float am0 = fmaxf(rmaxf[lrow], 1e-20f);
            const float am1 = fmaxf(rmaxf[lrow + 8], 1e-20f);
            const float inv0 = 127.0f / am0, inv1 = 127.0f / am1;
            if (wn == 0 && tg == 0) {
                osc[grow * 16 + seg]       = am0 * (1.0f / 127.0f);
                osc[(grow + 8) * 16 + seg] = am1 * (1.0f / 127.0f);
            }
#pragma unroll
            for (int nt = 0; nt < 4; ++nt) {
                const int colg = bx * 128 + wn * 32 + nt * 8 + 2 * tg;
                const int colo = seg * 128 + wn * 32 + nt * 8 + 2 * tg;
                const float sb0 = sB[colg], sb1 = sB[colg + 1];
                float v0 = sa0 * sb0 * ((float)accH[mt][nt][0] + (float)accM[mt][nt][0] * i256);
                float v1 = sa0 * sb1 * ((float)accH[mt][nt][1] + (float)accM[mt][nt][1] * i256);
                float v2 = sa8 * sb0 * ((float)accH[mt][nt][2] + (float)accM[mt][nt][2] * i256);
                float v3 = sa8 * sb1 * ((float)accH[mt][nt][3] + (float)accM[mt][nt][3] * i256);
                int8_t h0, l0, h1, l1;
                quant2(v0, inv0, h0, l0); quant2(v1, inv0, h1, l1);
                *(char2*)(o1 + grow * D_DIM + colo) = make_char2(h0, h1);
                *(char2*)(o2 + grow * D_DIM + colo) = make_char2(l0, l1);
                quant2(v2, inv1, h0, l0); quant2(v3, inv1, h1, l1);
                *(char2*)(o1 + (grow + 8) * D_DIM + colo) = make_char2(h0, h1);
                *(char2*)(o2 + (grow + 8) * D_DIM + colo) = make_char2(l0, l1);
            }
        }
        return;
    }

#pragma unroll
    for (int mt = 0; mt < 2; ++mt) {
        const int row = by * 128 + wm * 32 + mt * 16 + g;
        const float sa0 = sA[row], sa8 = sA[row + 8];
        float rm0 = 0.f, rm1 = 0.f;
#pragma unroll
        for (int nt = 0; nt < 4; ++nt) {
            const int col = bx * 128 + wn * 32 + nt * 8 + 2 * tg;
            const float sb0 = sB[col], sb1 = sB[col + 1];
            float v0 = sa0 * sb0 * ((float)accH[mt][nt][0] + (float)accM[mt][nt][0] * i256);
            float v1 = sa0 * sb1 * ((float)accH[mt][nt][1] + (float)accM[mt][nt][1] * i256);
            float v2 = sa8 * sb0 * ((float)accH[mt][nt][2] + (float)accM[mt][nt][2] * i256);
            float v3 = sa8 * sb1 * ((float)accH[mt][nt][3] + (float)accM[mt][nt][3] * i256);
            if (EPI == 2) {
                *(__nv_bfloat162*)(Obf + (size_t)row * Nd + col) =
                    __nv_bfloat162(__float2bfloat16_rn(v0), __float2bfloat16_rn(v1));
                *(__nv_bfloat162*)(Obf + (size_t)(row + 8) * Nd + col) =
                    __nv_bfloat162(__float2bfloat16_rn(v2), __float2bfloat16_rn(v3));
            } else {
                if (HAS_BIAS) {
                    float2 b2v = *(const float2*)(bias + col);
                    v0 += b2v.x; v1 += b2v.y; v2 += b2v.x; v3 += b2v.y;
                }
                if (RELU) {
                    v0 = fmaxf(v0, 0.f); v1 = fmaxf(v1, 0.f);
                    v2 = fmaxf(v2, 0.f); v3 = fmaxf(v3, 0.f);
                }
                if (HAS_RES) {
                    float2 ra = *(const float2*)(res + (size_t)row * Nd + col);
                    float2 rb = *(const float2*)(res + (size_t)(row + 8) * Nd + col);
                    v0 += ra.x; v1 += ra.y; v2 += rb.x; v3 += rb.y;
                }
                if (ROWMAX) {
                    rm0 = fmaxf(rm0, fmaxf(fabsf(v0), fabsf(v1)));
                    rm1 = fmaxf(rm1, fmaxf(fabsf(v2), fabsf(v3)));
                }
                *(float2*)(Cf + (size_t)row * Nd + col)       = make_float2(v0, v1);
                *(float2*)(Cf + (size_t)(row + 8) * Nd + col) = make_float2(v2, v3);
            }
        }
        if (EPI == 0 && ROWMAX) {
            rm0 = fmaxf(rm0, __shfl_xor_sync(0xffffffffu, rm0, 1));
            rm0 = fmaxf(rm0, __shfl_xor_sync(0xffffffffu, rm0, 2));
            rm1 = fmaxf(rm1, __shfl_xor_sync(0xffffffffu, rm1, 1));
            rm1 = fmaxf(rm1, __shfl_xor_sync(0xffffffffu, rm1, 2));
            if (tg == 0) {
                atomicMax((unsigned int*)&rowmax[row],     __float_as_uint(rm0));
                atomicMax((unsigned int*)&rowmax[row + 8], __float_as_uint(rm1));
            }
        }
    }
#undef ISSUE_I8
}

// ===========================================================================
// Tensor-core flash attention (QUIRK layout); epilogue feeds row absmax.
// ===========================================================================
#define AQ_H  0
#define AQ_L  18432
#define AK_H(bf) (36864 + (bf) * 18432)
#define AK_L(bf) (AK_H(bf) + 9216)
#define AVT(bf)  (73728 + (bf) * 18432)
#define APS_H 110592
#define APS_L 129024
#define ASQ   147456
#define ASK(bf) (147968 + (bf) * 256)
#define ATT_SMEM 148480

__global__ __launch_bounds__(256)
void attn_i8(const int8_t* __restrict__ Qq1, const int8_t* __restrict__ Qq2,
             const float* __restrict__ Qs,
             const int8_t* __restrict__ Kq1, const int8_t* __restrict__ Kq2,
             const float* __restrict__ Ks,
             const bf16* __restrict__ VT, float* __restrict__ O,
             float* __restrict__ rowmax)
{
    extern __shared__ char smem[];
    const uint32_t sb = smem_u32(smem);
    float* sQf = (float*)(smem + ASQ);
    const int qt   = blockIdx.x;
    const int head = blockIdx.y;
    const int b    = blockIdx.z;
    const int tid  = threadIdx.x;
    const int warp = tid >> 5;
    const int lane = tid & 31;
    const int l15  = lane & 15;
    const int lhalf = lane >> 4;
    const int g  = lane >> 2;
    const int tg = lane & 3;
    const int mrow = warp * 16;
    const int ntiles = 2 * qt + 2;
    const int bh = b * NH + head;
    const size_t hbase = (size_t)bh * S_LEN * HD;
    const int i0 = qt * 128;
    const bf16* vth = VT + (size_t)bh * HD * S_LEN;

    if (tid < 128) sQf[tid] = Qs[(size_t)bh * S_LEN + i0 + tid];

#pragma unroll
    for (int i = 0; i < 4; ++i) {
        int id = tid + 256 * i;
        int r = id >> 3, c = (id & 7) * 16;
        cpa16(sb + AQ_H + r * 144 + c, Qq1 + hbase + (size_t)(i0 + r) * HD + c);
        cpa16(sb + AQ_L + r * 144 + c, Qq2 + hbase + (size_t)(i0 + r) * HD + c);
    }

#define ATT_ISSUE(bf_, jt_) do { \
    const size_t kj0_ = (size_t)(jt_) * 64; \
    for (int i_ = tid; i_ < 512; i_ += 256) { \
        int r_ = i_ >> 3, c_ = (i_ & 7) * 16; \
        cpa16(sb + AK_H(bf_) + r_ * 144 + c_, Kq1 + hbase + (kj0_ + r_) * HD + c_); \
        cpa16(sb + AK_L(bf_) + r_ * 144 + c_, Kq2 + hbase + (kj0_ + r_) * HD + c_); \
    } \
    for (int i_ = tid; i_ < 1024; i_ += 256) { \
        int r_ = i_ >> 3, c_ = (i_ & 7) * 16; \
        cpa16(sb + AVT(bf_) + r_ * 144 + c_, \
              (const char*)(vth + (size_t)r_ * S_LEN + kj0_) + c_); \
    } \
    if (tid < 64) ((float*)(smem + ASK(bf_)))[tid] = Ks[(size_t)bh * S_LEN + kj0_ + tid]; \
} while (0)

    ATT_ISSUE(0, 0); CP_COMMIT();
    ATT_ISSUE(1, 1); CP_COMMIT();

    float o_acc[16][4];
#pragma unroll
    for (int ot = 0; ot < 16; ++ot)
#pragma unroll
        for (int e = 0; e < 4; ++e) o_acc[ot][e] = 0.f;
    float m0 = -1e30f, m1 = -1e30f, l0 = 0.f, l1 = 0.f;
    const float inv_sqrt_d = 0.08838834764831845f;
    const float inv256 = 0.00390625f;
    const int i_g0 = i0 + mrow + g;
    const int i_g1 = i_g0 + 8;

    const uint32_t qbH = sb + AQ_H + (mrow + l15) * 144 + lhalf * 16;
    const uint32_t qbL = sb + AQ_L + (mrow + l15) * 144 + lhalf * 16;
    const uint32_t pbH = sb + APS_H + (mrow + l15) * 144 + lhalf * 16;
    const uint32_t pbL = sb + APS_L + (mrow + l15) * 144 + lhalf * 16;

    for (int jt = 0; jt < ntiles; ++jt) {
        const int buf = jt & 1;
        CP_WAIT1();
        __syncthreads();
        const float* sKf = (const float*)(smem + ASK(buf));

        int accH[8][4], accM[8][4];
#pragma unroll
        for (int nt = 0; nt < 8; ++nt)
#pragma unroll
            for (int e = 0; e < 4; ++e) { accH[nt][e] = 0; accM[nt][e] = 0; }

#pragma unroll
        for (int ks = 0; ks < 4; ++ks) {
            uint32_t aH[4], aL[4];
            ldmx4(aH, qbH + ks * 32);
            ldmx4(aL, qbL + ks * 32);
#pragma unroll
            for (int ng = 0; ng < 4; ++ng) {
                uint32_t bH4[4], bL4[4];
                const uint32_t kaddr = (uint32_t)((ng * 16 + l15) * 144) + lhalf * 16 + ks * 32;
                ldmx4(bH4, sb + AK_H(buf) + kaddr);
                ldmx4(bL4, sb + AK_L(buf) + kaddr);
                mma_s8(accH[2 * ng],     aH, bH4[0], bH4[2]);
                mma_s8(accM[2 * ng],     aL, bH4[0], bH4[2]);
                mma_s8(accM[2 * ng],     aH, bL4[0], bL4[2]);
                mma_s8(accH[2 * ng + 1], aH, bH4[1], bH4[3]);
                mma_s8(accM[2 * ng + 1], aL, bH4[1], bH4[3]);
                mma_s8(accM[2 * ng + 1], aH, bL4[1], bL4[3]);
            }
        }

        const float sq0 = sQf[mrow + g], sq1 = sQf[mrow + g + 8];
        const bool diag = (jt >= 2 * qt);
        float sv[8][4];
        float rm0 = -1e30f, rm1 = -1e30f;
#pragma unroll
        for (int nt = 0; nt < 8; ++nt) {
            const int col0 = nt * 8 + 2 * tg;
            const float sk0 = sKf[col0], sk1 = sKf[col0 + 1];
            float s00 = sq0 * sk0 * ((float)accH[nt][0] + (float)accM[nt][0] * inv256);
            float s01 = sq0 * sk1 * ((float)accH[nt][1] + (float)accM[nt][1] * inv256);
            float s10 = sq1 * sk0 * ((float)accH[nt][2] + (float)accM[nt][2] * inv256);
            float s11 = sq1 * sk1 * ((float)accH[nt][3] + (float)accM[nt][3] * inv256);
            if (diag) {
                const int j0g = jt * 64 + col0;
                if (j0g     > i_g0) s00 = -1e9f;
                if (j0g + 1 > i_g0) s01 = -1e9f;
                if (j0g     > i_g1) s10 = -1e9f;
                if (j0g + 1 > i_g1) s11 = -1e9f;
            }
            s00 *= inv_sqrt_d; s01 *= inv_sqrt_d; s10 *= inv_sqrt_d; s11 *= inv_sqrt_d;
            sv[nt][0] = s00; sv[nt][1] = s01; sv[nt][2] = s10; sv[nt][3] = s11;
            rm0 = fmaxf(rm0, fmaxf(s00, s01));
            rm1 = fmaxf(rm1, fmaxf(s10, s11));
        }
        rm0 = fmaxf(rm0, __shfl_xor_sync(0xffffffffu, rm0, 1));
        rm0 = fmaxf(rm0, __shfl_xor_sync(0xffffffffu, rm0, 2));
        rm1 = fmaxf(rm1, __shfl_xor_sync(0xffffffffu, rm1, 1));
        rm1 = fmaxf(rm1, __shfl_xor_sync(0xffffffffu, rm1, 2));
        const float mn0 = fmaxf(m0, rm0), mn1 = fmaxf(m1, rm1);
        const float cr0 = __expf(m0 - mn0), cr1 = __expf(m1 - mn1);
        m0 = mn0; m1 = mn1;
        float rs0 = 0.f, rs1 = 0.f;
#pragma unroll
        for (int nt = 0; nt < 8; ++nt) {
            float p00 = __expf(sv[nt][0] - mn0);
            float p01 = __expf(sv[nt][1] - mn0);
            float p10 = __expf(sv[nt][2] - mn1);
            float p11 = __expf(sv[nt][3] - mn1);
            rs0 += p00 + p01; rs1 += p10 + p11;
            bf16 h00 = __float2bfloat16_rn(p00), h01 = __float2bfloat16_rn(p01);
            bf16 h10 = __float2bfloat16_rn(p10), h11 = __float2bfloat16_rn(p11);
            bf16 l00b = __float2bfloat16_rn(p00 - __bfloat162float(h00));
            bf16 l01b = __float2bfloat16_rn(p01 - __bfloat162float(h01));
            bf16 l10b = __float2bfloat16_rn(p10 - __bfloat162float(h10));
            bf16 l11b = __float2bfloat16_rn(p11 - __bfloat162float(h11));
            const uint32_t cofs = (uint32_t)((nt * 8 + 2 * tg) * 2);
            *(__nv_bfloat162*)(smem + APS_H + (mrow + g) * 144 + cofs)     = __nv_bfloat162(h00, h01);
            *(__nv_bfloat162*)(smem + APS_H + (mrow + g + 8) * 144 + cofs) = __nv_bfloat162(h10, h11);
            *(__nv_bfloat162*)(smem + APS_L + (mrow + g) * 144 + cofs)     = __nv_bfloat162(l00b, l01b);
            *(__nv_bfloat162*)(smem + APS_L + (mrow + g + 8) * 144 + cofs) = __nv_bfloat162(l10b, l11b);
        }
        rs0 += __shfl_xor_sync(0xffffffffu, rs0, 1);
        rs0 += __shfl_xor_sync(0xffffffffu, rs0, 2);
        rs1 += __shfl_xor_sync(0xffffffffu, rs1, 1);
        rs1 += __shfl_xor_sync(0xffffffffu, rs1, 2);
        l0 = l0 * cr0 + rs0;
        l1 = l1 * cr1 + rs1;
#pragma unroll
        for (int ot = 0; ot < 16; ++ot) {
            o_acc[ot][0] *= cr0; o_acc[ot][1] *= cr0;
            o_acc[ot][2] *= cr1; o_acc[ot][3] *= cr1;
        }
        __syncwarp();

#pragma unroll
        for (int ks = 0; ks < 4; ++ks) {
            uint32_t aH[4], aL[4];
            ldmx4(aH, pbH + ks * 32);
            ldmx4(aL, pbL + ks * 32);
#pragma unroll
            for (int vg = 0; vg < 8; ++vg) {
                uint32_t vb[4];
                ldmx4(vb, sb + AVT(buf) + (uint32_t)((vg * 16 + l15) * 144) + lhalf * 16 + ks * 32);
                mma_bf16(o_acc[2 * vg],     aH, vb[0], vb[2]);
                mma_bf16(o_acc[2 * vg],     aL, vb[0], vb[2]);
                mma_bf16(o_acc[2 * vg + 1], aH, vb[1], vb[3]);
                mma_bf16(o_acc[2 * vg + 1], aL, vb[1], vb[3]);
            }
        }
        __syncthreads();
        if (jt + 2 < ntiles) { ATT_ISSUE(buf, jt + 2); }
        CP_COMMIT();
    }

    const float li0 = 1.0f / l0, li1 = 1.0f / l1;
    const size_t grow0 = (size_t)b * S_LEN + i0 + mrow + g;
    float* orow0 = O + grow0       * D_DIM + head * HD;
    float* orow1 = O + (grow0 + 8) * D_DIM + head * HD;
    float am0 = 0.f, am1 = 0.f;
#pragma unroll
    for (int ot = 0; ot < 16; ++ot) {
        const int col = ot * 8 + 2 * tg;
        float a0 = o_acc[ot][0] * li0, a1 = o_acc[ot][1] * li0;
        float a2 = o_acc[ot][2] * li1, a3 = o_acc[ot][3] * li1;
        am0 = fmaxf(am0, fmaxf(fabsf(a0), fabsf(a1)));
        am1 = fmaxf(am1, fmaxf(fabsf(a2), fabsf(a3)));
        *(float2*)(orow0 + col) = make_float2(a0, a1);
        *(float2*)(orow1 + col) = make_float2(a2, a3);
    }
    am0 = fmaxf(am0, __shfl_xor_sync(0xffffffffu, am0, 1));
    am0 = fmaxf(am0, __shfl_xor_sync(0xffffffffu, am0, 2));
    am1 = fmaxf(am1, __shfl_xor_sync(0xffffffffu, am1, 1));
    am1 = fmaxf(am1, __shfl_xor_sync(0xffffffffu, am1, 2));
    if (tg == 0) {
        atomicMax((unsigned int*)&rowmax[grow0],     __float_as_uint(am0));
        atomicMax((unsigned int*)&rowmax[grow0 + 8], __float_as_uint(am1));
    }
#undef ATT_ISSUE
}

// ===========================================================================
// Launch — main chain on stream 0; Wv/Wo/W1/W2 prep forked to side stream.
// ===========================================================================
extern "C" void kernel_launch(void* const* d_in, const int* in_sizes, int n_in,
                              void* d_out, int out_size)
{
    (void)in_sizes; (void)n_in; (void)out_size;
    const float* x    = (const float*)d_in[0];
    const float* Wq   = (const float*)d_in[2];
    const float* Wk   = (const float*)d_in[3];
    const float* Wv   = (const float*)d_in[4];
    const float* Wo   = (const float*)d_in[5];
    const float* ln1g = (const float*)d_in[6];
    const float* ln1b = (const float*)d_in[7];
    const float* W1   = (const float*)d_in[8];
    const float* b1   = (const float*)d_in[9];
    const float* W2   = (const float*)d_in[10];
    const float* b2   = (const float*)d_in[11];
    const float* ln2g = (const float*)d_in[12];
    const float* ln2b = (const float*)d_in[13];
    float* out = (float*)d_out;

    int8_t *hq1, *hq2, *atq1, *atq2, *ffq1, *ffq2;
    float *hs, *ats, *ffs, *atrm, *ffrm;
    float *attn, *x2, *ff;
    int8_t *qq1, *qq2, *kq1, *kq2;
    float *qsc, *ksc;
    bf16 *vbf, *vt;
    int8_t *wqkq1, *wqkq2, *wvq1, *wvq2, *woq1, *woq2, *w1q1, *w1q2, *w2q1, *w2q2;
    float *wqks, *wqam, *wkam, *wvam, *wvs, *woam, *wos, *w1am, *w1s, *w2am, *w2s;
    cudaGetSymbolAddress((void**)&hq1,  g_h_q1);
    cudaGetSymbolAddress((void**)&hq2,  g_h_q2);
    cudaGetSymbolAddress((void**)&hs,   g_h_s);
    cudaGetSymbolAddress((void**)&attn, g_attn);
    cudaGetSymbolAddress((void**)&atq1, g_at_q1);
    cudaGetSymbolAddress((void**)&atq2, g_at_q2);
    cudaGetSymbolAddress((void**)&ats,  g_at_s);
    cudaGetSymbolAddress((void**)&atrm, g_at_rm);
    cudaGetSymbolAddress((void**)&x2,   g_x2);
    cudaGetSymbolAddress((void**)&ff,   g_ff);
    cudaGetSymbolAddress((void**)&ffq1, g_ff_q1);
    cudaGetSymbolAddress((void**)&ffq2, g_ff_q2);
    cudaGetSymbolAddress((void**)&ffs,  g_ff_s);
    cudaGetSymbolAddress((void**)&ffrm, g_ff_rm);
    cudaGetSymbolAddress((void**)&qq1,  g_q_q1);
    cudaGetSymbolAddress((void**)&qq2,  g_q_q2);
    cudaGetSymbolAddress((void**)&qsc,  g_q_sc);
    cudaGetSymbolAddress((void**)&kq1,  g_k_q1);
    cudaGetSymbolAddress((void**)&kq2,  g_k_q2);
    cudaGetSymbolAddress((void**)&ksc,  g_k_sc);
    cudaGetSymbolAddress((void**)&vbf,  g_vbf);
    cudaGetSymbolAddress((void**)&vt,   g_vt);
    cudaGetSymbolAddress((void**)&wqkq1, g_wqk_q1);
    cudaGetSymbolAddress((void**)&wqkq2, g_wqk_q2);
    cudaGetSymbolAddress((void**)&wqks,  g_wqk_s);
    cudaGetSymbolAddress((void**)&wqam,  g_wq_am);
    cudaGetSymbolAddress((void**)&wkam,  g_wk_am);
    cudaGetSymbolAddress((void**)&wvq1, g_wv_q1);
    cudaGetSymbolAddress((void**)&wvq2, g_wv_q2);
    cudaGetSymbolAddress((void**)&wvam, g_wv_am);
    cudaGetSymbolAddress((void**)&wvs,  g_wv_s);
    cudaGetSymbolAddress((void**)&woq1, g_wo_q1);
    cudaGetSymbolAddress((void**)&woq2, g_wo_q2);
    cudaGetSymbolAddress((void**)&woam, g_wo_am);
    cudaGetSymbolAddress((void**)&wos,  g_wo_s);
    cudaGetSymbolAddress((void**)&w1q1, g_w1_q1);
    cudaGetSymbolAddress((void**)&w1q2, g_w1_q2);
    cudaGetSymbolAddress((void**)&w1am, g_w1_am);
    cudaGetSymbolAddress((void**)&w1s,  g_w1_s);
    cudaGetSymbolAddress((void**)&w2q1, g_w2_q1);
    cudaGetSymbolAddress((void**)&w2q2, g_w2_q2);
    cudaGetSymbolAddress((void**)&w2am, g_w2_am);
    cudaGetSymbolAddress((void**)&w2s,  g_w2_s);

    cudaFuncSetAttribute(attn_i8,
                         cudaFuncAttributeMaxDynamicSharedMemorySize, ATT_SMEM);
    cudaFuncSetAttribute(gemm_i8<0, false, false, true, false>,
                         cudaFuncAttributeMaxDynamicSharedMemorySize, I8_SMEM);
    cudaFuncSetAttribute(gemm_i8<0, true, true, false, true>,
                         cudaFuncAttributeMaxDynamicSharedMemorySize, I8_SMEM);
    cudaFuncSetAttribute(gemm_i8<0, false, true, true, false>,
                         cudaFuncAttributeMaxDynamicSharedMemorySize, I8_SMEM);
    cudaFuncSetAttribute(gemm_i8<1, false, false, false, false>,
                         cudaFuncAttributeMaxDynamicSharedMemorySize, I8_SMEM);
    cudaFuncSetAttribute(gemm_i8<2, false, false, false, false>,
                         cudaFuncAttributeMaxDynamicSharedMemorySize, I8_SMEM);

    const dim3 blk(256);
    const dim3 blkG(512);
    const dim3 gQK(32, 32);
    const dim3 gDD(D_DIM / 128, ROWS / 128);
    const dim3 gDM(M_FF / 128,  ROWS / 128);
    cudaStream_t s1 = g_ps.s1;

    // ---- fork: side stream preps Wv, Wo, W1, W2 while main runs ln1+QK ----
    cudaEventRecord(g_ps.e0, 0);
    cudaStreamWaitEvent(s1, g_ps.e0, 0);

    // side stream
    cudaMemsetAsync(wvam, 0, D_DIM * sizeof(float), s1);
    colamax_kernel<<<dim3(64, 64), blk, 0, s1>>>(Wv, D_DIM, D_DIM, wvam);
    transpose_quant_i8<<<dim3(64, 64), blk, 0, s1>>>(Wv, wvam, wvq1, wvq2, wvs, D_DIM, D_DIM);
    cudaEventRecord(g_ps.evV, s1);
    cudaMemsetAsync(woam, 0, D_DIM * sizeof(float), s1);
    colamax_kernel<<<dim3(64, 64), blk, 0, s1>>>(Wo, D_DIM, D_DIM, woam);
    transpose_quant_i8<<<dim3(64, 64), blk, 0, s1>>>(Wo, woam, woq1, woq2, wos, D_DIM, D_DIM);
    cudaEventRecord(g_ps.evO, s1);
    cudaMemsetAsync(w1am, 0, M_FF * sizeof(float), s1);
    colamax_kernel<<<dim3(M_FF / 32, D_DIM / 32), blk, 0, s1>>>(W1, D_DIM, M_FF, w1am);
    transpose_quant_i8<<<dim3(256, 64), blk, 0, s1>>>(W1, w1am, w1q1, w1q2, w1s, D_DIM, M_FF);
    cudaEventRecord(g_ps.ev1, s1);
    cudaMemsetAsync(w2am, 0, D_DIM * sizeof(float), s1);
    colamax_kernel<<<dim3(D_DIM / 32, M_FF / 32), blk, 0, s1>>>(W2, M_FF, D_DIM, w2am);
    transpose_quant_i8<<<dim3(64, 256), blk, 0, s1>>>(W2, w2am, w2q1, w2q2, w2s, M_FF, D_DIM);
    cudaEventRecord(g_ps.ev2, s1);

    // main stream: critical path
    cudaMemsetAsync(atrm, 0, ROWS * sizeof(float));
    cudaMemsetAsync(ffrm, 0, ROWS * sizeof(float));
    cudaMemsetAsync(wqam, 0, D_DIM * sizeof(float));
    cudaMemsetAsync(wkam, 0, D_DIM * sizeof(float));
    ln_quant_i8<<<ROWS, blk>>>(x, ln1g, ln1b, hq1, hq2, hs);
    colamax_kernel<<<dim3(64, 64), blk>>>(Wq, D_DIM, D_DIM, wqam);
    colamax_kernel<<<dim3(64, 64), blk>>>(Wk, D_DIM, D_DIM, wkam);
    transpose_quant_i8<<<dim3(64, 64), blk>>>(Wq, wqam, wqkq1, wqkq2, wqks, D_DIM, D_DIM);
    transpose_quant_i8<<<dim3(64, 64), blk>>>(Wk, wkam,
        wqkq1 + (size_t)D_DIM * D_DIM, wqkq2 + (size_t)D_DIM * D_DIM,
        wqks + D_DIM, D_DIM, D_DIM);
    gemm_i8<1, false, false, false, false><<<gQK, blkG, I8_SMEM>>>(
        hq1, hq2, wqkq1, wqkq2, hs, wqks, nullptr, nullptr, nullptr, nullptr, nullptr,
        qq1, qq2, qsc, kq1, kq2, ksc, 2 * D_DIM, D_DIM);
    cudaStreamWaitEvent(0, g_ps.evV, 0);
    gemm_i8<2, false, false, false, false><<<gDD, blkG, I8_SMEM>>>(
        hq1, hq2, wvq1, wvq2, hs, wvs, nullptr, nullptr, nullptr, vbf, nullptr,
        nullptr, nullptr, nullptr, nullptr, nullptr, nullptr, D_DIM, D_DIM);
    vt_split<<<dim3(S_LEN / 32, HD / 32, B_SZ * NH), blk>>>(vbf, vt);
    attn_i8<<<dim3(S_LEN / 128, NH, B_SZ), blk, ATT_SMEM>>>(
        qq1, qq2, qsc, kq1, kq2, ksc, vt, attn, atrm);
    rowquant_pre<<<ROWS, blk>>>(attn, D_DIM, atrm, atq1, atq2, ats);
    cudaStreamWaitEvent(0, g_ps.evO, 0);
    gemm_i8<0, false, false, true, false><<<gDD, blkG, I8_SMEM>>>(
        atq1, atq2, woq1, woq2, ats, wos, nullptr, x, x2, nullptr, nullptr,
        nullptr, nullptr, nullptr, nullptr, nullptr, nullptr, D_DIM, D_DIM);
    ln_quant_i8<<<ROWS, blk>>>(x2, ln2g, ln2b, hq1, hq2, hs);
    cudaStreamWaitEvent(0, g_ps.ev1, 0);
    gemm_i8<0, true, true, false, true><<<gDM, blkG, I8_SMEM>>>(
        hq1, hq2, w1q1, w1q2, hs, w1s, b1, nullptr, ff, nullptr, ffrm,
        nullptr, nullptr, nullptr, nullptr, nullptr, nullptr, M_FF, D_DIM);
    rowquant_pre<<<ROWS, blk>>>(ff, M_FF, ffrm, ffq1, ffq2, ffs);
    cudaStreamWaitEvent(0, g_ps.ev2, 0);
    gemm_i8<0, false, true, true, false><<<gDD, blkG, I8_SMEM>>>(
        ffq1, ffq2, w2q1, w2q2, ffs, w2s, b2, x2, out, nullptr, nullptr,
        nullptr, nullptr, nullptr, nullptr, nullptr, nullptr, D_DIM, M_FF);
}